// round 8
// baseline (speedup 1.0000x reference)
#include <cuda_runtime.h>
#include <math.h>

#define Nn   50000
#define Ee   1600000
#define INF  128
#define OUTF 64
#define NIDX 5000
#define NBLK 196   // ceil(Nn/256)

// ---------------- scratch (device globals) ----------------------------------
__device__ float4 g_h4[Nn * 16];
__device__ float  g_s[Nn];
__device__ float  g_t[Nn];
__device__ float4 g_agg4[Nn * 16];
__device__ float4 g_hp4[Nn * 16];
__device__ float  g_rowsum[Nn];
__device__ float  g_nadd[Nn];
__device__ float  g_nrev[Nn];
__device__ float4 g_gamtab4[256 * 16];
__device__ float4 g_bettab4[256 * 16];
__device__ float  g_ngamtab[256];
__device__ float  g_nbettab[256];
__device__ float  g_Wt[INF * OUTF];
__device__ float  g_WaT[OUTF * OUTF];
__device__ float  g_WrT[OUTF * OUTF];
__device__ int    g_cnt[Nn];
__device__ int    g_off[Nn + 1];
__device__ int    g_cur[Nn];
__device__ int    g_dsts[Ee];
__device__ int    g_bsum[NBLK];
__device__ int    g_boff[NBLK];
__device__ unsigned long long g_degsum;

__device__ __forceinline__ float lrelu(float v) { return v > 0.f ? v : 0.01f * v; }

// ---------------- T: transpose weights + zero counters ----------------------
__global__ void k_trans(const float* __restrict__ W, const float* __restrict__ Wa,
                        const float* __restrict__ Wr) {
    int t = blockIdx.x * 256 + threadIdx.x;   // 64 blocks = 16384 threads
    if (t < 8192) {
        int k = t >> 6, j = t & 63;
        g_Wt[t] = W[j * 128 + k];
    } else if (t < 12288) {
        int p = t - 8192; int k = p >> 6, j = p & 63;
        g_WaT[p] = Wa[j * 64 + k];
    } else {
        int p = t - 12288; int k = p >> 6, j = p & 63;
        g_WrT[p] = Wr[j * 64 + k];
    }
    if (t == 0) g_degsum = 0ULL;
}

__global__ void k_zero() {
    int i = blockIdx.x * 256 + threadIdx.x;
    if (i < Nn) g_cnt[i] = 0;
}

// ---------------- H0: histogram of src + degree sum -------------------------
__global__ void k_hist(const int* __restrict__ edge, const int* __restrict__ degree) {
    int t = blockIdx.x * 256 + threadIdx.x;
    if (t < Ee) atomicAdd(&g_cnt[edge[t]], 1);
    if (t < NBLK * 256) {
        unsigned long long d = (t < Nn) ? (unsigned long long)(unsigned)degree[t] : 0ULL;
        #pragma unroll
        for (int o = 16; o; o >>= 1) d += __shfl_down_sync(0xFFFFFFFFu, d, o);
        if ((threadIdx.x & 31) == 0 && d) atomicAdd(&g_degsum, d);
    }
}

// ---------------- S1: per-block sums ----------------------------------------
__global__ void k_scan1() {
    __shared__ int ws[8];
    int i = blockIdx.x * 256 + threadIdx.x;
    int v = (i < Nn) ? g_cnt[i] : 0;
    int s = v;
    #pragma unroll
    for (int o = 16; o; o >>= 1) s += __shfl_down_sync(0xFFFFFFFFu, s, o);
    int lane = threadIdx.x & 31, w = threadIdx.x >> 5;
    if (lane == 0) ws[w] = s;
    __syncthreads();
    if (threadIdx.x == 0) {
        int t = 0;
        #pragma unroll
        for (int q = 0; q < 8; q++) t += ws[q];
        g_bsum[blockIdx.x] = t;
    }
}

// ---------------- S2: scan of block sums (1 block, 256 thr) ------------------
__global__ void k_scan2() {
    __shared__ int ws[8];
    int tid = threadIdx.x;
    int v = (tid < NBLK) ? g_bsum[tid] : 0;
    int orig = v;
    int lane = tid & 31, w = tid >> 5;
    #pragma unroll
    for (int o = 1; o < 32; o <<= 1) { int u = __shfl_up_sync(0xFFFFFFFFu, v, o); if (lane >= o) v += u; }
    if (lane == 31) ws[w] = v;
    __syncthreads();
    if (w == 0 && lane < 8) {
        int u = ws[lane];
        #pragma unroll
        for (int o = 1; o < 8; o <<= 1) { int z = __shfl_up_sync(0xFFu, u, o); if (lane >= o) u += z; }
        ws[lane] = u;
    }
    __syncthreads();
    int incl = v + (w ? ws[w - 1] : 0);
    if (tid < NBLK) g_boff[tid] = incl - orig;     // exclusive
    if (tid == NBLK - 1) g_off[Nn] = incl;
}

// ---------------- S3: local block scan + base --------------------------------
__global__ void k_scan3() {
    __shared__ int ws[8];
    int i = blockIdx.x * 256 + threadIdx.x;
    int v = (i < Nn) ? g_cnt[i] : 0;
    int orig = v;
    int lane = threadIdx.x & 31, w = threadIdx.x >> 5;
    #pragma unroll
    for (int o = 1; o < 32; o <<= 1) { int u = __shfl_up_sync(0xFFFFFFFFu, v, o); if (lane >= o) v += u; }
    if (lane == 31) ws[w] = v;
    __syncthreads();
    if (w == 0 && lane < 8) {
        int u = ws[lane];
        #pragma unroll
        for (int o = 1; o < 8; o <<= 1) { int z = __shfl_up_sync(0xFFu, u, o); if (lane >= o) u += z; }
        ws[lane] = u;
    }
    __syncthreads();
    int excl = v - orig + (w ? ws[w - 1] : 0) + g_boff[blockIdx.x];
    if (i < Nn) { g_off[i] = excl; g_cur[i] = excl; }
}

// ---------------- C: scatter dst into CSR slots -----------------------------
__global__ void k_scatter(const int* __restrict__ edge) {
    int t = blockIdx.x * 256 + threadIdx.x;
    if (t >= Ee) return;
    int src = edge[t];
    int dst = edge[Ee + t];
    int p = atomicAdd(&g_cur[src], 1);
    g_dsts[p] = dst;
}

// ---------------- H: h = (xW^T+b)*8 ; s,t projections -----------------------
__global__ void __launch_bounds__(256) k_h(const float* __restrict__ x,
                                           const float* __restrict__ b,
                                           const float* __restrict__ a) {
    __shared__ float4 Ws[128 * 16];
    __shared__ float4 xs[32 * 32];
    int tid = threadIdx.x;
    const float4* Wt4 = (const float4*)g_Wt;
    for (int p = tid; p < 128 * 16; p += 256) Ws[p] = Wt4[p];
    int n0 = blockIdx.x * 32;
    const float4* x4 = (const float4*)x;
    for (int p = tid; p < 32 * 32; p += 256) {
        int n = p >> 5, kq = p & 31;
        int node = n0 + n;
        xs[p] = (node < Nn) ? x4[node * 32 + kq] : make_float4(0.f, 0.f, 0.f, 0.f);
    }
    __syncthreads();

    int og = tid & 15, ng = tid >> 4;
    int na = 2 * ng, nb = na + 1;
    float4 A = make_float4(0.f, 0.f, 0.f, 0.f), B = A;
    #pragma unroll 4
    for (int kq = 0; kq < 32; kq++) {
        float4 w0 = Ws[(4 * kq + 0) * 16 + og];
        float4 w1 = Ws[(4 * kq + 1) * 16 + og];
        float4 w2 = Ws[(4 * kq + 2) * 16 + og];
        float4 w3 = Ws[(4 * kq + 3) * 16 + og];
        float4 xa = xs[na * 32 + kq];
        float4 xb = xs[nb * 32 + kq];
        A.x += xa.x * w0.x + xa.y * w1.x + xa.z * w2.x + xa.w * w3.x;
        A.y += xa.x * w0.y + xa.y * w1.y + xa.z * w2.y + xa.w * w3.y;
        A.z += xa.x * w0.z + xa.y * w1.z + xa.z * w2.z + xa.w * w3.z;
        A.w += xa.x * w0.w + xa.y * w1.w + xa.z * w2.w + xa.w * w3.w;
        B.x += xb.x * w0.x + xb.y * w1.x + xb.z * w2.x + xb.w * w3.x;
        B.y += xb.x * w0.y + xb.y * w1.y + xb.z * w2.y + xb.w * w3.y;
        B.z += xb.x * w0.z + xb.y * w1.z + xb.z * w2.z + xb.w * w3.z;
        B.w += xb.x * w0.w + xb.y * w1.w + xb.z * w2.w + xb.w * w3.w;
    }
    float4 b4 = ((const float4*)b)[og];
    float4 ha = make_float4((A.x + b4.x) * 8.f, (A.y + b4.y) * 8.f,
                            (A.z + b4.z) * 8.f, (A.w + b4.w) * 8.f);
    float4 hb = make_float4((B.x + b4.x) * 8.f, (B.y + b4.y) * 8.f,
                            (B.z + b4.z) * 8.f, (B.w + b4.w) * 8.f);
    int nodeA = n0 + na, nodeB = n0 + nb;
    if (nodeA < Nn) g_h4[nodeA * 16 + og] = ha;
    if (nodeB < Nn) g_h4[nodeB * 16 + og] = hb;

    float4 as4 = ((const float4*)a)[og];
    float4 at4 = ((const float4*)a)[16 + og];
    float sa = ha.x * as4.x + ha.y * as4.y + ha.z * as4.z + ha.w * as4.w;
    float ta = ha.x * at4.x + ha.y * at4.y + ha.z * at4.z + ha.w * at4.w;
    float sb = hb.x * as4.x + hb.y * as4.y + hb.z * as4.z + hb.w * as4.w;
    float tb = hb.x * at4.x + hb.y * at4.y + hb.z * at4.z + hb.w * at4.w;
    #pragma unroll
    for (int o = 8; o; o >>= 1) {
        sa += __shfl_down_sync(0xFFFFFFFFu, sa, o, 16);
        ta += __shfl_down_sync(0xFFFFFFFFu, ta, o, 16);
        sb += __shfl_down_sync(0xFFFFFFFFu, sb, o, 16);
        tb += __shfl_down_sync(0xFFFFFFFFu, tb, o, 16);
    }
    if (og == 0) {
        if (nodeA < Nn) { g_s[nodeA] = sa; g_t[nodeA] = ta; }
        if (nodeB < Nn) { g_s[nodeB] = sb; g_t[nodeB] = tb; }
    }
}

// ---------------- G: gamma/beta tables over 256 degrees ---------------------
__global__ void k_gbtab(const float* __restrict__ Wg_, const float* __restrict__ Wb_,
                        const float* __restrict__ bg, const float* __restrict__ bb,
                        const float* __restrict__ PE) {
    __shared__ float Wg[4096], Wb[4096];
    __shared__ float ms[4][64];
    __shared__ float pG[8], pB[8];
    int tid = threadIdx.x;
    for (int p = tid; p < 4096; p += 256) { Wg[p] = Wg_[p]; Wb[p] = Wb_[p]; }
    int local = tid >> 6, j = tid & 63;
    int d = blockIdx.x * 4 + local;
    ms[local][j] = PE[d * 64 + j];
    __syncthreads();
    float ag = bg[j], ab = bb[j];
    #pragma unroll
    for (int k = 0; k < 64; k++) {
        float m = ms[local][k];
        ag += m * Wg[k * 64 + j];
        ab += m * Wb[k * 64 + j];
    }
    float gam = lrelu(ag), bet = lrelu(ab);
    ((float*)g_gamtab4)[d * 64 + j] = gam;
    ((float*)g_bettab4)[d * 64 + j] = bet;
    float pg = gam * gam, pb = bet * bet;
    #pragma unroll
    for (int o = 16; o; o >>= 1) {
        pg += __shfl_down_sync(0xFFFFFFFFu, pg, o);
        pb += __shfl_down_sync(0xFFFFFFFFu, pb, o);
    }
    int w = tid >> 5;
    if ((tid & 31) == 0) { pG[w] = pg; pB[w] = pb; }
    __syncthreads();
    if (j == 0) {
        g_ngamtab[d] = sqrtf(pG[2 * local] + pG[2 * local + 1]);
        g_nbettab[d] = sqrtf(pB[2 * local] + pB[2 * local + 1]);
    }
}

// ---------------- A: gather aggregation (one warp per node, float2) ---------
__global__ void __launch_bounds__(256) k_gather() {
    int warp = (blockIdx.x * 256 + threadIdx.x) >> 5;
    if (warp >= Nn) return;
    int lane = threadIdx.x & 31;
    int s0 = g_off[warp], s1 = g_off[warp + 1];
    float ssrc = g_s[warp];
    const float2* h2 = (const float2*)g_h4;
    float2 acc = make_float2(0.f, 0.f);
    float2 wacc = make_float2(0.f, 0.f);
    float rs = 0.f;
    for (int base = s0; base < s1; base += 32) {
        int m = s1 - base; if (m > 32) m = 32;
        int dst = 0; float ev = 0.f;
        if (lane < m) {
            dst = g_dsts[base + lane];
            float z = ssrc + g_t[dst];
            ev = __expf(-(z > 0.f ? z : 0.01f * z));
            rs += ev;
        }
        for (int q = 0; q < m; q++) {
            int  d = __shfl_sync(0xFFFFFFFFu, dst, q);
            float e = __shfl_sync(0xFFFFFFFFu, ev, q);
            float2 v = h2[d * 32 + lane];
            acc.x += v.x;        acc.y += v.y;
            wacc.x += e * v.x;   wacc.y += e * v.y;
        }
    }
    ((float2*)g_agg4)[warp * 32 + lane] = acc;
    ((float2*)g_hp4)[warp * 32 + lane]  = wacc;
    #pragma unroll
    for (int o = 16; o; o >>= 1) rs += __shfl_down_sync(0xFFFFFFFFu, rs, o);
    if (lane == 0) g_rowsum[warp] = rs;
}

// ---------------- F: epilogue GEMMs + output + node norms -------------------
__global__ void __launch_bounds__(256) k_final(const int* __restrict__ degree,
                                               float* __restrict__ out) {
    __shared__ float4 WsA[64 * 16];
    __shared__ float4 WsR[64 * 16];
    __shared__ float4 is[32 * 16];
    __shared__ int   degs[32];
    int tid = threadIdx.x;
    const float4* Wa4 = (const float4*)g_WaT;
    const float4* Wr4 = (const float4*)g_WrT;
    for (int p = tid; p < 64 * 16; p += 256) { WsA[p] = Wa4[p]; WsR[p] = Wr4[p]; }
    int n0 = blockIdx.x * 32;
    if (tid < 32) {
        int node = n0 + tid;
        degs[tid] = (node < Nn) ? degree[node] : 1;
    }
    __syncthreads();
    for (int p = tid; p < 32 * 16; p += 256) {
        int n = p >> 4, kq = p & 15;
        int node = n0 + n;
        int d = degs[n];
        float inv = (d == 0) ? 0.f : 1.f / (float)d;
        float4 v = (node < Nn) ? g_agg4[node * 16 + kq] : make_float4(0.f, 0.f, 0.f, 0.f);
        is[p] = make_float4(v.x * inv, v.y * inv, v.z * inv, v.w * inv);
    }
    __syncthreads();

    int og = tid & 15, ng = tid >> 4;
    int na = 2 * ng, nb = na + 1;
    float4 Aa = make_float4(0.f, 0.f, 0.f, 0.f), Ra = Aa, Ab = Aa, Rb = Aa;
    #pragma unroll 4
    for (int kq = 0; kq < 16; kq++) {
        float4 xa = is[na * 16 + kq];
        float4 xb = is[nb * 16 + kq];
        #pragma unroll
        for (int r = 0; r < 4; r++) {
            float4 wa = WsA[(4 * kq + r) * 16 + og];
            float4 wr = WsR[(4 * kq + r) * 16 + og];
            float xav = (r == 0) ? xa.x : (r == 1) ? xa.y : (r == 2) ? xa.z : xa.w;
            float xbv = (r == 0) ? xb.x : (r == 1) ? xb.y : (r == 2) ? xb.z : xb.w;
            Aa.x += xav * wa.x; Aa.y += xav * wa.y; Aa.z += xav * wa.z; Aa.w += xav * wa.w;
            Ra.x += xav * wr.x; Ra.y += xav * wr.y; Ra.z += xav * wr.z; Ra.w += xav * wr.w;
            Ab.x += xbv * wa.x; Ab.y += xbv * wa.y; Ab.z += xbv * wa.z; Ab.w += xbv * wa.w;
            Rb.x += xbv * wr.x; Rb.y += xbv * wr.y; Rb.z += xbv * wr.z; Rb.w += xbv * wr.w;
        }
    }
    float Kthr = (float)((double)g_degsum / (double)Nn);

    #pragma unroll
    for (int half = 0; half < 2; half++) {
        int node = n0 + (half ? nb : na);
        float4 Av = half ? Ab : Aa;
        float4 Rv = half ? Rb : Ra;
        float pa = 0.f, pr = 0.f;
        float4 o4 = make_float4(0.f, 0.f, 0.f, 0.f);
        if (node < Nn) {
            int d = degs[half ? nb : na];
            float4 gam = g_gamtab4[d * 16 + og];
            float4 bet = g_bettab4[d * 16 + og];
            float4 ba, br;
            ba.x = (gam.x + 1.f) * Av.x + bet.x;  br.x = (gam.x + 1.f) * Rv.x + bet.x;
            ba.y = (gam.y + 1.f) * Av.y + bet.y;  br.y = (gam.y + 1.f) * Rv.y + bet.y;
            ba.z = (gam.z + 1.f) * Av.z + bet.z;  br.z = (gam.z + 1.f) * Rv.z + bet.z;
            ba.w = (gam.w + 1.f) * Av.w + bet.w;  br.w = (gam.w + 1.f) * Rv.w + bet.w;
            float R = ((float)d < Kthr) ? 1.f : 0.f;
            float4 hp = g_hp4[node * 16 + og];
            float inv = 1.f / (g_rowsum[node] + 1e-5f + 1.f);
            float bx = 0.1f * (R * ba.x - (1.f - R) * br.x);
            float by = 0.1f * (R * ba.y - (1.f - R) * br.y);
            float bz = 0.1f * (R * ba.z - (1.f - R) * br.z);
            float bw = 0.1f * (R * ba.w - (1.f - R) * br.w);
            o4.x = lrelu((hp.x + bx) * inv);
            o4.y = lrelu((hp.y + by) * inv);
            o4.z = lrelu((hp.z + bz) * inv);
            o4.w = lrelu((hp.w + bw) * inv);
            pa = ba.x * ba.x + ba.y * ba.y + ba.z * ba.z + ba.w * ba.w;
            pr = br.x * br.x + br.y * br.y + br.z * br.z + br.w * br.w;
        }
        #pragma unroll
        for (int o = 8; o; o >>= 1) {
            pa += __shfl_down_sync(0xFFFFFFFFu, pa, o, 16);
            pr += __shfl_down_sync(0xFFFFFFFFu, pr, o, 16);
        }
        if (node < Nn) {
            ((float4*)out)[node * 16 + og] = o4;
            if (og == 0) { g_nadd[node] = sqrtf(pa); g_nrev[node] = sqrtf(pr); }
        }
    }
}

// ---------------- L: loss reductions over idx -------------------------------
__global__ void k_loss(const int* __restrict__ degree, const int* __restrict__ idx,
                       float* __restrict__ out) {
    __shared__ float sb[256], sf[256];
    float Kthr = (float)((double)g_degsum / (double)Nn);
    float lb = 0.f, lf = 0.f;
    for (int i = threadIdx.x; i < NIDX; i += 256) {
        int r = idx[i];
        int d = degree[r];
        bool R = ((float)d) < Kthr;
        lb += R ? g_nadd[r] : g_nrev[r];
        lf += g_ngamtab[d] + g_nbettab[d];
    }
    sb[threadIdx.x] = lb; sf[threadIdx.x] = lf;
    __syncthreads();
    for (int s = 128; s; s >>= 1) {
        if (threadIdx.x < (unsigned)s) {
            sb[threadIdx.x] += sb[threadIdx.x + s];
            sf[threadIdx.x] += sf[threadIdx.x + s];
        }
        __syncthreads();
    }
    if (threadIdx.x == 0) {
        out[Nn * OUTF]     = sb[0] / (float)NIDX;
        out[Nn * OUTF + 1] = sf[0] / (float)NIDX;
    }
}

// ---------------- launch -----------------------------------------------------
extern "C" void kernel_launch(void* const* d_in, const int* in_sizes, int n_in,
                              void* d_out, int out_size) {
    const float* x      = (const float*)d_in[0];
    const float* W      = (const float*)d_in[1];
    const float* b      = (const float*)d_in[2];
    const float* a      = (const float*)d_in[3];
    const float* Wg     = (const float*)d_in[4];
    const float* Wb     = (const float*)d_in[5];
    const float* bg     = (const float*)d_in[6];
    const float* bb     = (const float*)d_in[7];
    const float* Wadd   = (const float*)d_in[8];
    const float* Wrev   = (const float*)d_in[9];
    const float* PE     = (const float*)d_in[10];
    const int*   edge   = (const int*)d_in[11];
    const int*   degree = (const int*)d_in[12];
    const int*   idx    = (const int*)d_in[13];
    float* out = (float*)d_out;

    k_trans<<<64, 256>>>(W, Wadd, Wrev);
    k_zero<<<NBLK, 256>>>();
    k_hist<<<Ee / 256, 256>>>(edge, degree);
    k_scan1<<<NBLK, 256>>>();
    k_scan2<<<1, 256>>>();
    k_scan3<<<NBLK, 256>>>();
    k_scatter<<<Ee / 256, 256>>>(edge);
    k_h<<<(Nn + 31) / 32, 256>>>(x, b, a);
    k_gbtab<<<64, 256>>>(Wg, Wb, bg, bb, PE);
    k_gather<<<(Nn * 32 + 255) / 256, 256>>>();
    k_final<<<(Nn + 31) / 32, 256>>>(degree, out);
    if (out_size >= Nn * OUTF + 2)
        k_loss<<<1, 256>>>(degree, idx, out);
}

// round 9
// speedup vs baseline: 1.0882x; 1.0882x over previous
#include <cuda_runtime.h>
#include <math.h>

#define Nn   50000
#define Ee   1600000
#define INF  128
#define OUTF 64
#define NIDX 5000
#define NBLK 196        // ceil(Nn/256)
#define HBLK 1563       // ceil(Nn/32)
#define SBLK 1563       // ceil(Ee/4/256)

// ---------------- scratch (device globals) ----------------------------------
__device__ float4 g_h4[Nn * 16];
__device__ float  g_s[Nn];
__device__ float  g_t[Nn];
__device__ float  g_nadd[Nn];
__device__ float  g_nrev[Nn];
__device__ float4 g_gamtab4[256 * 16];
__device__ float4 g_bettab4[256 * 16];
__device__ float  g_ngamtab[256];
__device__ float  g_nbettab[256];
__device__ float  g_Wt[INF * OUTF];
__device__ float  g_WaT[OUTF * OUTF];
__device__ float  g_WrT[OUTF * OUTF];
__device__ int    g_cnt[Nn];
__device__ int    g_off[Nn + 1];
__device__ int    g_cur[Nn];
__device__ int    g_dsts[Ee];
__device__ int    g_bsum[NBLK];
__device__ unsigned long long g_degsum;

__device__ __forceinline__ float lrelu(float v) { return v > 0.f ? v : 0.01f * v; }

// ---------------- P: transpose weights + zero counters + gamma/beta tables --
__global__ void k_pre(const float* __restrict__ W, const float* __restrict__ Wa,
                      const float* __restrict__ Wr, const float* __restrict__ Wg_,
                      const float* __restrict__ Wb_, const float* __restrict__ bg,
                      const float* __restrict__ bb, const float* __restrict__ PE) {
    int blk = blockIdx.x, tid = threadIdx.x;
    if (blk < 64) {                              // weight transposes
        int t = blk * 256 + tid;
        if (t < 8192) {
            int k = t >> 6, j = t & 63;
            g_Wt[t] = W[j * 128 + k];
        } else if (t < 12288) {
            int p = t - 8192; int k = p >> 6, j = p & 63;
            g_WaT[p] = Wa[j * 64 + k];
        } else {
            int p = t - 12288; int k = p >> 6, j = p & 63;
            g_WrT[p] = Wr[j * 64 + k];
        }
        if (t == 0) g_degsum = 0ULL;
        return;
    }
    if (blk < 64 + NBLK) {                       // zero histogram counters
        int i = (blk - 64) * 256 + tid;
        if (i < Nn) g_cnt[i] = 0;
        return;
    }
    // gamma/beta table over 256 degrees
    __shared__ float Wg[4096], Wb[4096];
    __shared__ float ms[4][64];
    __shared__ float pG[8], pB[8];
    for (int p = tid; p < 4096; p += 256) { Wg[p] = Wg_[p]; Wb[p] = Wb_[p]; }
    int local = tid >> 6, j = tid & 63;
    int d = (blk - 64 - NBLK) * 4 + local;       // 64 blocks -> 256 degrees
    ms[local][j] = PE[d * 64 + j];
    __syncthreads();
    float ag = bg[j], ab = bb[j];
    #pragma unroll
    for (int k = 0; k < 64; k++) {
        float m = ms[local][k];
        ag += m * Wg[k * 64 + j];
        ab += m * Wb[k * 64 + j];
    }
    float gam = lrelu(ag), bet = lrelu(ab);
    ((float*)g_gamtab4)[d * 64 + j] = gam;
    ((float*)g_bettab4)[d * 64 + j] = bet;
    float pg = gam * gam, pb = bet * bet;
    #pragma unroll
    for (int o = 16; o; o >>= 1) {
        pg += __shfl_down_sync(0xFFFFFFFFu, pg, o);
        pb += __shfl_down_sync(0xFFFFFFFFu, pb, o);
    }
    int w = tid >> 5;
    if ((tid & 31) == 0) { pG[w] = pg; pB[w] = pb; }
    __syncthreads();
    if (j == 0) {
        g_ngamtab[d] = sqrtf(pG[2 * local] + pG[2 * local + 1]);
        g_nbettab[d] = sqrtf(pB[2 * local] + pB[2 * local + 1]);
    }
}

// ---------------- H0: histogram of src (int4) + degree sum ------------------
__global__ void k_hist(const int* __restrict__ edge, const int* __restrict__ degree) {
    int blk = blockIdx.x;
    if (blk < SBLK) {
        int t = blk * 256 + threadIdx.x;
        if (t < Ee / 4) {
            int4 e = ((const int4*)edge)[t];
            atomicAdd(&g_cnt[e.x], 1);
            atomicAdd(&g_cnt[e.y], 1);
            atomicAdd(&g_cnt[e.z], 1);
            atomicAdd(&g_cnt[e.w], 1);
        }
        return;
    }
    int t = (blk - SBLK) * 256 + threadIdx.x;
    unsigned long long d = (t < Nn) ? (unsigned long long)(unsigned)degree[t] : 0ULL;
    #pragma unroll
    for (int o = 16; o; o >>= 1) d += __shfl_down_sync(0xFFFFFFFFu, d, o);
    if ((threadIdx.x & 31) == 0 && d) atomicAdd(&g_degsum, d);
}

// ---------------- S1: per-block sums ----------------------------------------
__global__ void k_scan1() {
    __shared__ int ws[8];
    int i = blockIdx.x * 256 + threadIdx.x;
    int v = (i < Nn) ? g_cnt[i] : 0;
    int s = v;
    #pragma unroll
    for (int o = 16; o; o >>= 1) s += __shfl_down_sync(0xFFFFFFFFu, s, o);
    int lane = threadIdx.x & 31, w = threadIdx.x >> 5;
    if (lane == 0) ws[w] = s;
    __syncthreads();
    if (threadIdx.x == 0) {
        int t = 0;
        #pragma unroll
        for (int q = 0; q < 8; q++) t += ws[q];
        g_bsum[blockIdx.x] = t;
    }
}

// ---------------- S3: replicated block-sum scan + local scan -----------------
__global__ void k_scan3b() {
    __shared__ int ws[8];
    __shared__ int base_s, tot_s;
    int tid = threadIdx.x;
    int lane = tid & 31, w = tid >> 5;
    // phase 1: every block scans the 196 block sums (cheap, removes a launch)
    {
        int v = (tid < NBLK) ? g_bsum[tid] : 0;
        int orig = v;
        #pragma unroll
        for (int o = 1; o < 32; o <<= 1) { int u = __shfl_up_sync(0xFFFFFFFFu, v, o); if (lane >= o) v += u; }
        if (lane == 31) ws[w] = v;
        __syncthreads();
        if (w == 0 && lane < 8) {
            int u = ws[lane];
            #pragma unroll
            for (int o = 1; o < 8; o <<= 1) { int z = __shfl_up_sync(0xFFu, u, o); if (lane >= o) u += z; }
            ws[lane] = u;
        }
        __syncthreads();
        int incl = v + (w ? ws[w - 1] : 0);
        if (tid == (int)blockIdx.x) base_s = incl - orig;
        if (tid == NBLK - 1) tot_s = incl;
        __syncthreads();
    }
    // phase 2: local scan of this block's counts
    int i = blockIdx.x * 256 + tid;
    int c = (i < Nn) ? g_cnt[i] : 0;
    int corig = c;
    #pragma unroll
    for (int o = 1; o < 32; o <<= 1) { int u = __shfl_up_sync(0xFFFFFFFFu, c, o); if (lane >= o) c += u; }
    if (lane == 31) ws[w] = c;
    __syncthreads();
    if (w == 0 && lane < 8) {
        int u = ws[lane];
        #pragma unroll
        for (int o = 1; o < 8; o <<= 1) { int z = __shfl_up_sync(0xFFu, u, o); if (lane >= o) u += z; }
        ws[lane] = u;
    }
    __syncthreads();
    int excl = c - corig + (w ? ws[w - 1] : 0) + base_s;
    if (i < Nn) { g_off[i] = excl; g_cur[i] = excl; }
    if (blockIdx.x == 0 && tid == 0) g_off[Nn] = tot_s;
}

// ---------------- SH: scatter (int4) co-scheduled with h-GEMM ---------------
__global__ void __launch_bounds__(256) k_sh(const int* __restrict__ edge,
                                            const float* __restrict__ x,
                                            const float* __restrict__ b,
                                            const float* __restrict__ a) {
    __shared__ float4 Ws[128 * 16];   // 32KB (h branch only)
    __shared__ float4 xs[32 * 32];    // 16KB
    if (blockIdx.x < SBLK) {          // -------- scatter branch --------
        int t = blockIdx.x * 256 + threadIdx.x;
        if (t < Ee / 4) {
            int4 s4 = ((const int4*)edge)[t];
            int4 d4 = ((const int4*)(edge + Ee))[t];
            int p;
            p = atomicAdd(&g_cur[s4.x], 1); g_dsts[p] = d4.x;
            p = atomicAdd(&g_cur[s4.y], 1); g_dsts[p] = d4.y;
            p = atomicAdd(&g_cur[s4.z], 1); g_dsts[p] = d4.z;
            p = atomicAdd(&g_cur[s4.w], 1); g_dsts[p] = d4.w;
        }
        return;
    }
    // -------- h = (xW^T+b)*8 ; s,t projections --------
    int tid = threadIdx.x;
    const float4* Wt4 = (const float4*)g_Wt;
    for (int p = tid; p < 128 * 16; p += 256) Ws[p] = Wt4[p];
    int n0 = (blockIdx.x - SBLK) * 32;
    const float4* x4 = (const float4*)x;
    for (int p = tid; p < 32 * 32; p += 256) {
        int n = p >> 5, kq = p & 31;
        int node = n0 + n;
        xs[p] = (node < Nn) ? x4[node * 32 + kq] : make_float4(0.f, 0.f, 0.f, 0.f);
    }
    __syncthreads();

    int og = tid & 15, ng = tid >> 4;
    int na = 2 * ng, nb = na + 1;
    float4 A = make_float4(0.f, 0.f, 0.f, 0.f), B = A;
    #pragma unroll 4
    for (int kq = 0; kq < 32; kq++) {
        float4 w0 = Ws[(4 * kq + 0) * 16 + og];
        float4 w1 = Ws[(4 * kq + 1) * 16 + og];
        float4 w2 = Ws[(4 * kq + 2) * 16 + og];
        float4 w3 = Ws[(4 * kq + 3) * 16 + og];
        float4 xa = xs[na * 32 + kq];
        float4 xb = xs[nb * 32 + kq];
        A.x += xa.x * w0.x + xa.y * w1.x + xa.z * w2.x + xa.w * w3.x;
        A.y += xa.x * w0.y + xa.y * w1.y + xa.z * w2.y + xa.w * w3.y;
        A.z += xa.x * w0.z + xa.y * w1.z + xa.z * w2.z + xa.w * w3.z;
        A.w += xa.x * w0.w + xa.y * w1.w + xa.z * w2.w + xa.w * w3.w;
        B.x += xb.x * w0.x + xb.y * w1.x + xb.z * w2.x + xb.w * w3.x;
        B.y += xb.x * w0.y + xb.y * w1.y + xb.z * w2.y + xb.w * w3.y;
        B.z += xb.x * w0.z + xb.y * w1.z + xb.z * w2.z + xb.w * w3.z;
        B.w += xb.x * w0.w + xb.y * w1.w + xb.z * w2.w + xb.w * w3.w;
    }
    float4 b4 = ((const float4*)b)[og];
    float4 ha = make_float4((A.x + b4.x) * 8.f, (A.y + b4.y) * 8.f,
                            (A.z + b4.z) * 8.f, (A.w + b4.w) * 8.f);
    float4 hb = make_float4((B.x + b4.x) * 8.f, (B.y + b4.y) * 8.f,
                            (B.z + b4.z) * 8.f, (B.w + b4.w) * 8.f);
    int nodeA = n0 + na, nodeB = n0 + nb;
    if (nodeA < Nn) g_h4[nodeA * 16 + og] = ha;
    if (nodeB < Nn) g_h4[nodeB * 16 + og] = hb;

    float4 as4 = ((const float4*)a)[og];
    float4 at4 = ((const float4*)a)[16 + og];
    float sa = ha.x * as4.x + ha.y * as4.y + ha.z * as4.z + ha.w * as4.w;
    float ta = ha.x * at4.x + ha.y * at4.y + ha.z * at4.z + ha.w * at4.w;
    float sb = hb.x * as4.x + hb.y * as4.y + hb.z * as4.z + hb.w * as4.w;
    float tb = hb.x * at4.x + hb.y * at4.y + hb.z * at4.z + hb.w * at4.w;
    #pragma unroll
    for (int o = 8; o; o >>= 1) {
        sa += __shfl_down_sync(0xFFFFFFFFu, sa, o, 16);
        ta += __shfl_down_sync(0xFFFFFFFFu, ta, o, 16);
        sb += __shfl_down_sync(0xFFFFFFFFu, sb, o, 16);
        tb += __shfl_down_sync(0xFFFFFFFFu, tb, o, 16);
    }
    if (og == 0) {
        if (nodeA < Nn) { g_s[nodeA] = sa; g_t[nodeA] = ta; }
        if (nodeB < Nn) { g_s[nodeB] = sb; g_t[nodeB] = tb; }
    }
}

// ---------------- GF: fused gather + epilogue GEMM + output + norms ---------
#define GF_SMEM 49536
__global__ void __launch_bounds__(256) k_gf(const int* __restrict__ degree,
                                            float* __restrict__ out) {
    extern __shared__ float sm[];
    float4* WsA  = (float4*)sm;          // 4096 floats
    float4* WsR  = WsA + 1024;           // 4096 floats
    float*  sAgg = sm + 8192;            // 2048
    float*  sHp  = sAgg + 2048;          // 2048
    float*  sRs  = sHp + 2048;           // 32
    float*  sInv = sRs + 32;             // 32
    int*    sDeg = (int*)(sInv + 32);    // 32
    int tid = threadIdx.x;
    const float4* Wa4 = (const float4*)g_WaT;
    const float4* Wr4 = (const float4*)g_WrT;
    for (int p = tid; p < 1024; p += 256) { WsA[p] = Wa4[p]; WsR[p] = Wr4[p]; }
    int n0 = blockIdx.x * 32;
    if (tid < 32) {
        int node = n0 + tid;
        int d = (node < Nn) ? degree[node] : 1;
        sDeg[tid] = d;
        sInv[tid] = (d == 0) ? 0.f : 1.f / (float)d;
    }
    // ---- gather phase: warp w handles local nodes w, w+8, w+16, w+24 ----
    int w = tid >> 5, lane = tid & 31;
    const float2* h2 = (const float2*)g_h4;
    #pragma unroll
    for (int k = 0; k < 4; k++) {
        int nl = w + 8 * k;
        int node = n0 + nl;
        float2 acc = make_float2(0.f, 0.f), wacc = acc;
        float rs = 0.f;
        if (node < Nn) {
            int s0 = g_off[node], s1 = g_off[node + 1];
            float ssrc = g_s[node];
            for (int base = s0; base < s1; base += 32) {
                int m = s1 - base; if (m > 32) m = 32;
                int dst = 0; float ev = 0.f;
                if (lane < m) {
                    dst = g_dsts[base + lane];
                    float z = ssrc + g_t[dst];
                    ev = __expf(-(z > 0.f ? z : 0.01f * z));
                    rs += ev;
                }
                for (int q = 0; q < m; q++) {
                    int  dd = __shfl_sync(0xFFFFFFFFu, dst, q);
                    float e = __shfl_sync(0xFFFFFFFFu, ev, q);
                    float2 v = h2[dd * 32 + lane];
                    acc.x += v.x;       acc.y += v.y;
                    wacc.x += e * v.x;  wacc.y += e * v.y;
                }
            }
        }
        ((float2*)sAgg)[nl * 32 + lane] = acc;
        ((float2*)sHp)[nl * 32 + lane]  = wacc;
        #pragma unroll
        for (int o = 16; o; o >>= 1) rs += __shfl_down_sync(0xFFFFFFFFu, rs, o);
        if (lane == 0) sRs[nl] = rs;
    }
    __syncthreads();
    // normalize agg in place -> i
    for (int p = tid; p < 2048; p += 256) sAgg[p] *= sInv[p >> 6];
    __syncthreads();

    // ---- epilogue GEMM phase ----
    int og = tid & 15, ng = tid >> 4;
    int na = 2 * ng, nb = na + 1;
    const float4* is4 = (const float4*)sAgg;
    float4 Aa = make_float4(0.f, 0.f, 0.f, 0.f), Ra = Aa, Ab = Aa, Rb = Aa;
    #pragma unroll 4
    for (int kq = 0; kq < 16; kq++) {
        float4 xa = is4[na * 16 + kq];
        float4 xb = is4[nb * 16 + kq];
        #pragma unroll
        for (int r = 0; r < 4; r++) {
            float4 wa = WsA[(4 * kq + r) * 16 + og];
            float4 wr = WsR[(4 * kq + r) * 16 + og];
            float xav = (r == 0) ? xa.x : (r == 1) ? xa.y : (r == 2) ? xa.z : xa.w;
            float xbv = (r == 0) ? xb.x : (r == 1) ? xb.y : (r == 2) ? xb.z : xb.w;
            Aa.x += xav * wa.x; Aa.y += xav * wa.y; Aa.z += xav * wa.z; Aa.w += xav * wa.w;
            Ra.x += xav * wr.x; Ra.y += xav * wr.y; Ra.z += xav * wr.z; Ra.w += xav * wr.w;
            Ab.x += xbv * wa.x; Ab.y += xbv * wa.y; Ab.z += xbv * wa.z; Ab.w += xbv * wa.w;
            Rb.x += xbv * wr.x; Rb.y += xbv * wr.y; Rb.z += xbv * wr.z; Rb.w += xbv * wr.w;
        }
    }
    float Kthr = (float)((double)g_degsum / (double)Nn);

    #pragma unroll
    for (int half = 0; half < 2; half++) {
        int nl = half ? nb : na;
        int node = n0 + nl;
        float4 Av = half ? Ab : Aa;
        float4 Rv = half ? Rb : Ra;
        float pa = 0.f, pr = 0.f;
        float4 o4 = make_float4(0.f, 0.f, 0.f, 0.f);
        if (node < Nn) {
            int d = sDeg[nl];
            float4 gam = g_gamtab4[d * 16 + og];
            float4 bet = g_bettab4[d * 16 + og];
            float4 ba, br;
            ba.x = (gam.x + 1.f) * Av.x + bet.x;  br.x = (gam.x + 1.f) * Rv.x + bet.x;
            ba.y = (gam.y + 1.f) * Av.y + bet.y;  br.y = (gam.y + 1.f) * Rv.y + bet.y;
            ba.z = (gam.z + 1.f) * Av.z + bet.z;  br.z = (gam.z + 1.f) * Rv.z + bet.z;
            ba.w = (gam.w + 1.f) * Av.w + bet.w;  br.w = (gam.w + 1.f) * Rv.w + bet.w;
            float R = ((float)d < Kthr) ? 1.f : 0.f;
            const float4* hp4 = (const float4*)sHp;
            float4 hp = hp4[nl * 16 + og];
            float inv = 1.f / (sRs[nl] + 1e-5f + 1.f);
            float bx = 0.1f * (R * ba.x - (1.f - R) * br.x);
            float by = 0.1f * (R * ba.y - (1.f - R) * br.y);
            float bz = 0.1f * (R * ba.z - (1.f - R) * br.z);
            float bw = 0.1f * (R * ba.w - (1.f - R) * br.w);
            o4.x = lrelu((hp.x + bx) * inv);
            o4.y = lrelu((hp.y + by) * inv);
            o4.z = lrelu((hp.z + bz) * inv);
            o4.w = lrelu((hp.w + bw) * inv);
            pa = ba.x * ba.x + ba.y * ba.y + ba.z * ba.z + ba.w * ba.w;
            pr = br.x * br.x + br.y * br.y + br.z * br.z + br.w * br.w;
        }
        #pragma unroll
        for (int o = 8; o; o >>= 1) {
            pa += __shfl_down_sync(0xFFFFFFFFu, pa, o, 16);
            pr += __shfl_down_sync(0xFFFFFFFFu, pr, o, 16);
        }
        if (node < Nn) {
            ((float4*)out)[node * 16 + og] = o4;
            if (og == 0) { g_nadd[node] = sqrtf(pa); g_nrev[node] = sqrtf(pr); }
        }
    }
}

// ---------------- L: loss reductions over idx -------------------------------
__global__ void k_loss(const int* __restrict__ degree, const int* __restrict__ idx,
                       float* __restrict__ out) {
    __shared__ float sb[256], sf[256];
    float Kthr = (float)((double)g_degsum / (double)Nn);
    float lb = 0.f, lf = 0.f;
    for (int i = threadIdx.x; i < NIDX; i += 256) {
        int r = idx[i];
        int d = degree[r];
        bool R = ((float)d) < Kthr;
        lb += R ? g_nadd[r] : g_nrev[r];
        lf += g_ngamtab[d] + g_nbettab[d];
    }
    sb[threadIdx.x] = lb; sf[threadIdx.x] = lf;
    __syncthreads();
    for (int s = 128; s; s >>= 1) {
        if (threadIdx.x < (unsigned)s) {
            sb[threadIdx.x] += sb[threadIdx.x + s];
            sf[threadIdx.x] += sf[threadIdx.x + s];
        }
        __syncthreads();
    }
    if (threadIdx.x == 0) {
        out[Nn * OUTF]     = sb[0] / (float)NIDX;
        out[Nn * OUTF + 1] = sf[0] / (float)NIDX;
    }
}

// ---------------- launch -----------------------------------------------------
extern "C" void kernel_launch(void* const* d_in, const int* in_sizes, int n_in,
                              void* d_out, int out_size) {
    const float* x      = (const float*)d_in[0];
    const float* W      = (const float*)d_in[1];
    const float* b      = (const float*)d_in[2];
    const float* a      = (const float*)d_in[3];
    const float* Wg     = (const float*)d_in[4];
    const float* Wb     = (const float*)d_in[5];
    const float* bg     = (const float*)d_in[6];
    const float* bb     = (const float*)d_in[7];
    const float* Wadd   = (const float*)d_in[8];
    const float* Wrev   = (const float*)d_in[9];
    const float* PE     = (const float*)d_in[10];
    const int*   edge   = (const int*)d_in[11];
    const int*   degree = (const int*)d_in[12];
    const int*   idx    = (const int*)d_in[13];
    float* out = (float*)d_out;

    cudaFuncSetAttribute(k_gf, cudaFuncAttributeMaxDynamicSharedMemorySize, GF_SMEM);

    k_pre<<<64 + NBLK + 64, 256>>>(W, Wadd, Wrev, Wg, Wb, bg, bb, PE);
    k_hist<<<SBLK + NBLK, 256>>>(edge, degree);
    k_scan1<<<NBLK, 256>>>();
    k_scan3b<<<NBLK, 256>>>();
    k_sh<<<SBLK + HBLK, 256>>>(edge, x, b, a);
    k_gf<<<HBLK, 256, GF_SMEM>>>(degree, out);
    if (out_size >= Nn * OUTF + 2)
        k_loss<<<1, 256>>>(degree, idx, out);
}

// round 10
// speedup vs baseline: 1.1149x; 1.0246x over previous
#include <cuda_runtime.h>
#include <math.h>

#define Nn   50000
#define Ee   1600000
#define INF  128
#define OUTF 64
#define NIDX 5000
#define NBLK 196        // ceil(Nn/256)
#define HBLK 1563       // ceil(Nn/32)
#define SBLK 1563       // ceil(Ee/4/256)

// ---------------- scratch (device globals) ----------------------------------
__device__ float4 g_h4[Nn * 16];
__device__ float  g_s[Nn];
__device__ float  g_t[Nn];
__device__ float  g_nadd[Nn];
__device__ float  g_nrev[Nn];
__device__ float4 g_gamtab4[256 * 16];
__device__ float4 g_bettab4[256 * 16];
__device__ float  g_ngamtab[256];
__device__ float  g_nbettab[256];
__device__ float  g_Wt[INF * OUTF];
__device__ float  g_WaT[OUTF * OUTF];
__device__ float  g_WrT[OUTF * OUTF];
__device__ int    g_cnt[Nn];          // zero at module load; re-zeroed by k_scan3b
__device__ int    g_off[Nn + 1];
__device__ int    g_cur[Nn];
__device__ int    g_dsts[Ee];
__device__ int    g_bsum[NBLK];
__device__ int    g_dpart[NBLK];
__device__ float  g_Kthr;

__device__ __forceinline__ float lrelu(float v) { return v > 0.f ? v : 0.01f * v; }

// ---------------- PH: hist + degree partials + transposes + gbtab -----------
__global__ void k_ph(const int* __restrict__ edge, const int* __restrict__ degree,
                     const float* __restrict__ W, const float* __restrict__ Wa,
                     const float* __restrict__ Wr, const float* __restrict__ Wg_,
                     const float* __restrict__ Wb_, const float* __restrict__ bg,
                     const float* __restrict__ bb, const float* __restrict__ PE) {
    int blk = blockIdx.x, tid = threadIdx.x;
    if (blk < SBLK) {                             // ---- edge histogram (int4) ----
        int t = blk * 256 + tid;
        if (t < Ee / 4) {
            int4 e = ((const int4*)edge)[t];
            atomicAdd(&g_cnt[e.x], 1);
            atomicAdd(&g_cnt[e.y], 1);
            atomicAdd(&g_cnt[e.z], 1);
            atomicAdd(&g_cnt[e.w], 1);
        }
        return;
    }
    if (blk < SBLK + NBLK) {                      // ---- degree partial sums ----
        __shared__ int ws[8];
        int bb2 = blk - SBLK;
        int t = bb2 * 256 + tid;
        int d = (t < Nn) ? degree[t] : 0;
        #pragma unroll
        for (int o = 16; o; o >>= 1) d += __shfl_down_sync(0xFFFFFFFFu, d, o);
        int lane = tid & 31, w = tid >> 5;
        if (lane == 0) ws[w] = d;
        __syncthreads();
        if (tid == 0) {
            int s = 0;
            #pragma unroll
            for (int q = 0; q < 8; q++) s += ws[q];
            g_dpart[bb2] = s;
        }
        return;
    }
    if (blk < SBLK + NBLK + 64) {                 // ---- weight transposes ----
        int t = (blk - SBLK - NBLK) * 256 + tid;
        if (t < 8192) {
            int k = t >> 6, j = t & 63;
            g_Wt[t] = W[j * 128 + k];
        } else if (t < 12288) {
            int p = t - 8192; int k = p >> 6, j = p & 63;
            g_WaT[p] = Wa[j * 64 + k];
        } else {
            int p = t - 12288; int k = p >> 6, j = p & 63;
            g_WrT[p] = Wr[j * 64 + k];
        }
        return;
    }
    // ---- gamma/beta tables over 256 degrees ----
    __shared__ float Wg[4096], Wb[4096];
    __shared__ float ms[4][64];
    __shared__ float pG[8], pB[8];
    for (int p = tid; p < 4096; p += 256) { Wg[p] = Wg_[p]; Wb[p] = Wb_[p]; }
    int local = tid >> 6, j = tid & 63;
    int d = (blk - SBLK - NBLK - 64) * 4 + local;
    ms[local][j] = PE[d * 64 + j];
    __syncthreads();
    float ag = bg[j], ab = bb[j];
    #pragma unroll
    for (int k = 0; k < 64; k++) {
        float m = ms[local][k];
        ag += m * Wg[k * 64 + j];
        ab += m * Wb[k * 64 + j];
    }
    float gam = lrelu(ag), bet = lrelu(ab);
    ((float*)g_gamtab4)[d * 64 + j] = gam;
    ((float*)g_bettab4)[d * 64 + j] = bet;
    float pg = gam * gam, pb = bet * bet;
    #pragma unroll
    for (int o = 16; o; o >>= 1) {
        pg += __shfl_down_sync(0xFFFFFFFFu, pg, o);
        pb += __shfl_down_sync(0xFFFFFFFFu, pb, o);
    }
    int w = tid >> 5;
    if ((tid & 31) == 0) { pG[w] = pg; pB[w] = pb; }
    __syncthreads();
    if (j == 0) {
        g_ngamtab[d] = sqrtf(pG[2 * local] + pG[2 * local + 1]);
        g_nbettab[d] = sqrtf(pB[2 * local] + pB[2 * local + 1]);
    }
}

// ---------------- S1: per-block sums + degsum reduction ----------------------
__global__ void k_scan1() {
    __shared__ int ws[8];
    int tid = threadIdx.x;
    int lane = tid & 31, w = tid >> 5;
    if (blockIdx.x == NBLK) {                     // ---- Kthr from degree partials ----
        int v = (tid < NBLK) ? g_dpart[tid] : 0;
        #pragma unroll
        for (int o = 16; o; o >>= 1) v += __shfl_down_sync(0xFFFFFFFFu, v, o);
        if (lane == 0) ws[w] = v;
        __syncthreads();
        if (tid == 0) {
            int s = 0;
            #pragma unroll
            for (int q = 0; q < 8; q++) s += ws[q];
            g_Kthr = (float)((double)s / (double)Nn);
        }
        return;
    }
    int i = blockIdx.x * 256 + tid;
    int v = (i < Nn) ? g_cnt[i] : 0;
    int s = v;
    #pragma unroll
    for (int o = 16; o; o >>= 1) s += __shfl_down_sync(0xFFFFFFFFu, s, o);
    if (lane == 0) ws[w] = s;
    __syncthreads();
    if (tid == 0) {
        int t = 0;
        #pragma unroll
        for (int q = 0; q < 8; q++) t += ws[q];
        g_bsum[blockIdx.x] = t;
    }
}

// ---------------- S3: replicated block-sum scan + local scan + cnt re-zero ---
__global__ void k_scan3b() {
    __shared__ int ws[8];
    __shared__ int base_s, tot_s;
    int tid = threadIdx.x;
    int lane = tid & 31, w = tid >> 5;
    {
        int v = (tid < NBLK) ? g_bsum[tid] : 0;
        int orig = v;
        #pragma unroll
        for (int o = 1; o < 32; o <<= 1) { int u = __shfl_up_sync(0xFFFFFFFFu, v, o); if (lane >= o) v += u; }
        if (lane == 31) ws[w] = v;
        __syncthreads();
        if (w == 0 && lane < 8) {
            int u = ws[lane];
            #pragma unroll
            for (int o = 1; o < 8; o <<= 1) { int z = __shfl_up_sync(0xFFu, u, o); if (lane >= o) u += z; }
            ws[lane] = u;
        }
        __syncthreads();
        int incl = v + (w ? ws[w - 1] : 0);
        if (tid == (int)blockIdx.x) base_s = incl - orig;
        if (tid == NBLK - 1) tot_s = incl;
        __syncthreads();
    }
    int i = blockIdx.x * 256 + tid;
    int c = (i < Nn) ? g_cnt[i] : 0;
    int corig = c;
    #pragma unroll
    for (int o = 1; o < 32; o <<= 1) { int u = __shfl_up_sync(0xFFFFFFFFu, c, o); if (lane >= o) c += u; }
    if (lane == 31) ws[w] = c;
    __syncthreads();
    if (w == 0 && lane < 8) {
        int u = ws[lane];
        #pragma unroll
        for (int o = 1; o < 8; o <<= 1) { int z = __shfl_up_sync(0xFFu, u, o); if (lane >= o) u += z; }
        ws[lane] = u;
    }
    __syncthreads();
    int excl = c - corig + (w ? ws[w - 1] : 0) + base_s;
    if (i < Nn) {
        g_off[i] = excl; g_cur[i] = excl;
        g_cnt[i] = 0;                 // re-zero for next replay
    }
    if (blockIdx.x == 0 && tid == 0) g_off[Nn] = tot_s;
}

// ---------------- SH: scatter (int4) co-scheduled with h-GEMM ---------------
__global__ void __launch_bounds__(256) k_sh(const int* __restrict__ edge,
                                            const float* __restrict__ x,
                                            const float* __restrict__ b,
                                            const float* __restrict__ a) {
    __shared__ float4 Ws[128 * 16];
    __shared__ float4 xs[32 * 32];
    if (blockIdx.x < SBLK) {          // -------- scatter branch --------
        int t = blockIdx.x * 256 + threadIdx.x;
        if (t < Ee / 4) {
            int4 s4 = ((const int4*)edge)[t];
            int4 d4 = ((const int4*)(edge + Ee))[t];
            int p;
            p = atomicAdd(&g_cur[s4.x], 1); g_dsts[p] = d4.x;
            p = atomicAdd(&g_cur[s4.y], 1); g_dsts[p] = d4.y;
            p = atomicAdd(&g_cur[s4.z], 1); g_dsts[p] = d4.z;
            p = atomicAdd(&g_cur[s4.w], 1); g_dsts[p] = d4.w;
        }
        return;
    }
    // -------- h = (xW^T+b)*8 ; s,t projections --------
    int tid = threadIdx.x;
    const float4* Wt4 = (const float4*)g_Wt;
    for (int p = tid; p < 128 * 16; p += 256) Ws[p] = Wt4[p];
    int n0 = (blockIdx.x - SBLK) * 32;
    const float4* x4 = (const float4*)x;
    for (int p = tid; p < 32 * 32; p += 256) {
        int n = p >> 5, kq = p & 31;
        int node = n0 + n;
        xs[p] = (node < Nn) ? x4[node * 32 + kq] : make_float4(0.f, 0.f, 0.f, 0.f);
    }
    __syncthreads();

    int og = tid & 15, ng = tid >> 4;
    int na = 2 * ng, nb = na + 1;
    float4 A = make_float4(0.f, 0.f, 0.f, 0.f), B = A;
    #pragma unroll 4
    for (int kq = 0; kq < 32; kq++) {
        float4 w0 = Ws[(4 * kq + 0) * 16 + og];
        float4 w1 = Ws[(4 * kq + 1) * 16 + og];
        float4 w2 = Ws[(4 * kq + 2) * 16 + og];
        float4 w3 = Ws[(4 * kq + 3) * 16 + og];
        float4 xa = xs[na * 32 + kq];
        float4 xb = xs[nb * 32 + kq];
        A.x += xa.x * w0.x + xa.y * w1.x + xa.z * w2.x + xa.w * w3.x;
        A.y += xa.x * w0.y + xa.y * w1.y + xa.z * w2.y + xa.w * w3.y;
        A.z += xa.x * w0.z + xa.y * w1.z + xa.z * w2.z + xa.w * w3.z;
        A.w += xa.x * w0.w + xa.y * w1.w + xa.z * w2.w + xa.w * w3.w;
        B.x += xb.x * w0.x + xb.y * w1.x + xb.z * w2.x + xb.w * w3.x;
        B.y += xb.x * w0.y + xb.y * w1.y + xb.z * w2.y + xb.w * w3.y;
        B.z += xb.x * w0.z + xb.y * w1.z + xb.z * w2.z + xb.w * w3.z;
        B.w += xb.x * w0.w + xb.y * w1.w + xb.z * w2.w + xb.w * w3.w;
    }
    float4 b4 = ((const float4*)b)[og];
    float4 ha = make_float4((A.x + b4.x) * 8.f, (A.y + b4.y) * 8.f,
                            (A.z + b4.z) * 8.f, (A.w + b4.w) * 8.f);
    float4 hb = make_float4((B.x + b4.x) * 8.f, (B.y + b4.y) * 8.f,
                            (B.z + b4.z) * 8.f, (B.w + b4.w) * 8.f);
    int nodeA = n0 + na, nodeB = n0 + nb;
    if (nodeA < Nn) g_h4[nodeA * 16 + og] = ha;
    if (nodeB < Nn) g_h4[nodeB * 16 + og] = hb;

    float4 as4 = ((const float4*)a)[og];
    float4 at4 = ((const float4*)a)[16 + og];
    float sa = ha.x * as4.x + ha.y * as4.y + ha.z * as4.z + ha.w * as4.w;
    float ta = ha.x * at4.x + ha.y * at4.y + ha.z * at4.z + ha.w * at4.w;
    float sb = hb.x * as4.x + hb.y * as4.y + hb.z * as4.z + hb.w * as4.w;
    float tb = hb.x * at4.x + hb.y * at4.y + hb.z * at4.z + hb.w * at4.w;
    #pragma unroll
    for (int o = 8; o; o >>= 1) {
        sa += __shfl_down_sync(0xFFFFFFFFu, sa, o, 16);
        ta += __shfl_down_sync(0xFFFFFFFFu, ta, o, 16);
        sb += __shfl_down_sync(0xFFFFFFFFu, sb, o, 16);
        tb += __shfl_down_sync(0xFFFFFFFFu, tb, o, 16);
    }
    if (og == 0) {
        if (nodeA < Nn) { g_s[nodeA] = sa; g_t[nodeA] = ta; }
        if (nodeB < Nn) { g_s[nodeB] = sb; g_t[nodeB] = tb; }
    }
}

// ---------------- GF: fused gather + epilogue GEMM + output + norms ---------
#define GF_SMEM 49536
__global__ void __launch_bounds__(256) k_gf(const int* __restrict__ degree,
                                            float* __restrict__ out) {
    extern __shared__ float sm[];
    float4* WsA  = (float4*)sm;
    float4* WsR  = WsA + 1024;
    float*  sAgg = sm + 8192;
    float*  sHp  = sAgg + 2048;
    float*  sRs  = sHp + 2048;
    float*  sInv = sRs + 32;
    int*    sDeg = (int*)(sInv + 32);
    int tid = threadIdx.x;
    const float4* Wa4 = (const float4*)g_WaT;
    const float4* Wr4 = (const float4*)g_WrT;
    for (int p = tid; p < 1024; p += 256) { WsA[p] = Wa4[p]; WsR[p] = Wr4[p]; }
    int n0 = blockIdx.x * 32;
    if (tid < 32) {
        int node = n0 + tid;
        int d = (node < Nn) ? degree[node] : 1;
        sDeg[tid] = d;
        sInv[tid] = (d == 0) ? 0.f : 1.f / (float)d;
    }
    int w = tid >> 5, lane = tid & 31;
    const float2* h2 = (const float2*)g_h4;
    #pragma unroll
    for (int k = 0; k < 4; k++) {
        int nl = w + 8 * k;
        int node = n0 + nl;
        float2 acc = make_float2(0.f, 0.f), wacc = acc;
        float rs = 0.f;
        if (node < Nn) {
            int s0 = g_off[node], s1 = g_off[node + 1];
            float ssrc = g_s[node];
            for (int base = s0; base < s1; base += 32) {
                int m = s1 - base; if (m > 32) m = 32;
                int dst = 0; float ev = 0.f;
                if (lane < m) {
                    dst = g_dsts[base + lane];
                    float z = ssrc + g_t[dst];
                    ev = __expf(-(z > 0.f ? z : 0.01f * z));
                    rs += ev;
                }
                if (m == 32) {
                    #pragma unroll 8
                    for (int q = 0; q < 32; q++) {
                        int  dd = __shfl_sync(0xFFFFFFFFu, dst, q);
                        float e = __shfl_sync(0xFFFFFFFFu, ev, q);
                        float2 v = h2[dd * 32 + lane];
                        acc.x += v.x;       acc.y += v.y;
                        wacc.x += e * v.x;  wacc.y += e * v.y;
                    }
                } else {
                    for (int q = 0; q < m; q++) {
                        int  dd = __shfl_sync(0xFFFFFFFFu, dst, q);
                        float e = __shfl_sync(0xFFFFFFFFu, ev, q);
                        float2 v = h2[dd * 32 + lane];
                        acc.x += v.x;       acc.y += v.y;
                        wacc.x += e * v.x;  wacc.y += e * v.y;
                    }
                }
            }
        }
        ((float2*)sAgg)[nl * 32 + lane] = acc;
        ((float2*)sHp)[nl * 32 + lane]  = wacc;
        #pragma unroll
        for (int o = 16; o; o >>= 1) rs += __shfl_down_sync(0xFFFFFFFFu, rs, o);
        if (lane == 0) sRs[nl] = rs;
    }
    __syncthreads();
    for (int p = tid; p < 2048; p += 256) sAgg[p] *= sInv[p >> 6];
    __syncthreads();

    int og = tid & 15, ng = tid >> 4;
    int na = 2 * ng, nb = na + 1;
    const float4* is4 = (const float4*)sAgg;
    float4 Aa = make_float4(0.f, 0.f, 0.f, 0.f), Ra = Aa, Ab = Aa, Rb = Aa;
    #pragma unroll 4
    for (int kq = 0; kq < 16; kq++) {
        float4 xa = is4[na * 16 + kq];
        float4 xb = is4[nb * 16 + kq];
        #pragma unroll
        for (int r = 0; r < 4; r++) {
            float4 wa = WsA[(4 * kq + r) * 16 + og];
            float4 wr = WsR[(4 * kq + r) * 16 + og];
            float xav = (r == 0) ? xa.x : (r == 1) ? xa.y : (r == 2) ? xa.z : xa.w;
            float xbv = (r == 0) ? xb.x : (r == 1) ? xb.y : (r == 2) ? xb.z : xb.w;
            Aa.x += xav * wa.x; Aa.y += xav * wa.y; Aa.z += xav * wa.z; Aa.w += xav * wa.w;
            Ra.x += xav * wr.x; Ra.y += xav * wr.y; Ra.z += xav * wr.z; Ra.w += xav * wr.w;
            Ab.x += xbv * wa.x; Ab.y += xbv * wa.y; Ab.z += xbv * wa.z; Ab.w += xbv * wa.w;
            Rb.x += xbv * wr.x; Rb.y += xbv * wr.y; Rb.z += xbv * wr.z; Rb.w += xbv * wr.w;
        }
    }
    float Kthr = g_Kthr;

    #pragma unroll
    for (int half = 0; half < 2; half++) {
        int nl = half ? nb : na;
        int node = n0 + nl;
        float4 Av = half ? Ab : Aa;
        float4 Rv = half ? Rb : Ra;
        float pa = 0.f, pr = 0.f;
        float4 o4 = make_float4(0.f, 0.f, 0.f, 0.f);
        if (node < Nn) {
            int d = sDeg[nl];
            float4 gam = g_gamtab4[d * 16 + og];
            float4 bet = g_bettab4[d * 16 + og];
            float4 ba, br;
            ba.x = (gam.x + 1.f) * Av.x + bet.x;  br.x = (gam.x + 1.f) * Rv.x + bet.x;
            ba.y = (gam.y + 1.f) * Av.y + bet.y;  br.y = (gam.y + 1.f) * Rv.y + bet.y;
            ba.z = (gam.z + 1.f) * Av.z + bet.z;  br.z = (gam.z + 1.f) * Rv.z + bet.z;
            ba.w = (gam.w + 1.f) * Av.w + bet.w;  br.w = (gam.w + 1.f) * Rv.w + bet.w;
            float R = ((float)d < Kthr) ? 1.f : 0.f;
            const float4* hp4 = (const float4*)sHp;
            float4 hp = hp4[nl * 16 + og];
            float inv = 1.f / (sRs[nl] + 1e-5f + 1.f);
            float bx = 0.1f * (R * ba.x - (1.f - R) * br.x);
            float by = 0.1f * (R * ba.y - (1.f - R) * br.y);
            float bz = 0.1f * (R * ba.z - (1.f - R) * br.z);
            float bw = 0.1f * (R * ba.w - (1.f - R) * br.w);
            o4.x = lrelu((hp.x + bx) * inv);
            o4.y = lrelu((hp.y + by) * inv);
            o4.z = lrelu((hp.z + bz) * inv);
            o4.w = lrelu((hp.w + bw) * inv);
            pa = ba.x * ba.x + ba.y * ba.y + ba.z * ba.z + ba.w * ba.w;
            pr = br.x * br.x + br.y * br.y + br.z * br.z + br.w * br.w;
        }
        #pragma unroll
        for (int o = 8; o; o >>= 1) {
            pa += __shfl_down_sync(0xFFFFFFFFu, pa, o, 16);
            pr += __shfl_down_sync(0xFFFFFFFFu, pr, o, 16);
        }
        if (node < Nn) {
            ((float4*)out)[node * 16 + og] = o4;
            if (og == 0) { g_nadd[node] = sqrtf(pa); g_nrev[node] = sqrtf(pr); }
        }
    }
}

// ---------------- L: loss reductions over idx -------------------------------
__global__ void k_loss(const int* __restrict__ degree, const int* __restrict__ idx,
                       float* __restrict__ out) {
    __shared__ float sb[256], sf[256];
    float Kthr = g_Kthr;
    float lb = 0.f, lf = 0.f;
    for (int i = threadIdx.x; i < NIDX; i += 256) {
        int r = idx[i];
        int d = degree[r];
        bool R = ((float)d) < Kthr;
        lb += R ? g_nadd[r] : g_nrev[r];
        lf += g_ngamtab[d] + g_nbettab[d];
    }
    sb[threadIdx.x] = lb; sf[threadIdx.x] = lf;
    __syncthreads();
    for (int s = 128; s; s >>= 1) {
        if (threadIdx.x < (unsigned)s) {
            sb[threadIdx.x] += sb[threadIdx.x + s];
            sf[threadIdx.x] += sf[threadIdx.x + s];
        }
        __syncthreads();
    }
    if (threadIdx.x == 0) {
        out[Nn * OUTF]     = sb[0] / (float)NIDX;
        out[Nn * OUTF + 1] = sf[0] / (float)NIDX;
    }
}

// ---------------- launch -----------------------------------------------------
extern "C" void kernel_launch(void* const* d_in, const int* in_sizes, int n_in,
                              void* d_out, int out_size) {
    const float* x      = (const float*)d_in[0];
    const float* W      = (const float*)d_in[1];
    const float* b      = (const float*)d_in[2];
    const float* a      = (const float*)d_in[3];
    const float* Wg     = (const float*)d_in[4];
    const float* Wb     = (const float*)d_in[5];
    const float* bg     = (const float*)d_in[6];
    const float* bb     = (const float*)d_in[7];
    const float* Wadd   = (const float*)d_in[8];
    const float* Wrev   = (const float*)d_in[9];
    const float* PE     = (const float*)d_in[10];
    const int*   edge   = (const int*)d_in[11];
    const int*   degree = (const int*)d_in[12];
    const int*   idx    = (const int*)d_in[13];
    float* out = (float*)d_out;

    cudaFuncSetAttribute(k_gf, cudaFuncAttributeMaxDynamicSharedMemorySize, GF_SMEM);

    k_ph<<<SBLK + NBLK + 64 + 64, 256>>>(edge, degree, W, Wadd, Wrev, Wg, Wb, bg, bb, PE);
    k_scan1<<<NBLK + 1, 256>>>();
    k_scan3b<<<NBLK, 256>>>();
    k_sh<<<SBLK + HBLK, 256>>>(edge, x, b, a);
    k_gf<<<HBLK, 256, GF_SMEM>>>(degree, out);
    if (out_size >= Nn * OUTF + 2)
        k_loss<<<1, 256>>>(degree, idx, out);
}

// round 12
// speedup vs baseline: 1.1442x; 1.0263x over previous
#include <cuda_runtime.h>
#include <math.h>

#define Nn   50000
#define Ee   1600000
#define INF  128
#define OUTF 64
#define NIDX 5000
#define NBLK 196        // ceil(Nn/256)
#define HBLK2 782       // ceil(Nn/64)
#define GBLK 1563       // ceil(Nn/32)
#define SBLK 1563       // ceil(Ee/4/256)

// ---------------- scratch (device globals) ----------------------------------
__device__ float4 g_h4[Nn * 16];
__device__ float  g_s[Nn];
__device__ float  g_t[Nn];
__device__ float  g_nadd[Nn];
__device__ float  g_nrev[Nn];
__device__ float4 g_gamtab4[256 * 16];
__device__ float4 g_bettab4[256 * 16];
__device__ float  g_ngamtab[256];
__device__ float  g_nbettab[256];
__device__ float  g_Wt[INF * OUTF];
__device__ float  g_WaT[OUTF * OUTF];
__device__ float  g_WrT[OUTF * OUTF];
__device__ int    g_cnt[Nn];          // zero at module load; re-zeroed by k_scan3b
__device__ int    g_off[Nn + 1];
__device__ int    g_cur[Nn];
__device__ int    g_dsts[Ee];
__device__ int    g_bsum[NBLK];
__device__ int    g_dpart[NBLK];
__device__ float  g_Kthr;

__device__ __forceinline__ float lrelu(float v) { return v > 0.f ? v : 0.01f * v; }

// ---------------- PH: hist + degree partials + transposes + gbtab -----------
__global__ void k_ph(const int* __restrict__ edge, const int* __restrict__ degree,
                     const float* __restrict__ W, const float* __restrict__ Wa,
                     const float* __restrict__ Wr, const float* __restrict__ Wg_,
                     const float* __restrict__ Wb_, const float* __restrict__ bg,
                     const float* __restrict__ bb, const float* __restrict__ PE) {
    int blk = blockIdx.x, tid = threadIdx.x;
    if (blk < SBLK) {                             // ---- edge histogram (int4) ----
        int t = blk * 256 + tid;
        if (t < Ee / 4) {
            int4 e = ((const int4*)edge)[t];
            atomicAdd(&g_cnt[e.x], 1);
            atomicAdd(&g_cnt[e.y], 1);
            atomicAdd(&g_cnt[e.z], 1);
            atomicAdd(&g_cnt[e.w], 1);
        }
        return;
    }
    if (blk < SBLK + NBLK) {                      // ---- degree partial sums ----
        __shared__ int ws[8];
        int bb2 = blk - SBLK;
        int t = bb2 * 256 + tid;
        int d = (t < Nn) ? degree[t] : 0;
        #pragma unroll
        for (int o = 16; o; o >>= 1) d += __shfl_down_sync(0xFFFFFFFFu, d, o);
        int lane = tid & 31, w = tid >> 5;
        if (lane == 0) ws[w] = d;
        __syncthreads();
        if (tid == 0) {
            int s = 0;
            #pragma unroll
            for (int q = 0; q < 8; q++) s += ws[q];
            g_dpart[bb2] = s;
        }
        return;
    }
    if (blk < SBLK + NBLK + 64) {                 // ---- weight transposes ----
        int t = (blk - SBLK - NBLK) * 256 + tid;
        if (t < 8192) {
            int k = t >> 6, j = t & 63;
            g_Wt[t] = W[j * 128 + k];
        } else if (t < 12288) {
            int p = t - 8192; int k = p >> 6, j = p & 63;
            g_WaT[p] = Wa[j * 64 + k];
        } else {
            int p = t - 12288; int k = p >> 6, j = p & 63;
            g_WrT[p] = Wr[j * 64 + k];
        }
        return;
    }
    // ---- gamma/beta tables over 256 degrees ----
    __shared__ float Wg[4096], Wb[4096];
    __shared__ float ms[4][64];
    __shared__ float pG[8], pB[8];
    for (int p = tid; p < 4096; p += 256) { Wg[p] = Wg_[p]; Wb[p] = Wb_[p]; }
    int local = tid >> 6, j = tid & 63;
    int d = (blk - SBLK - NBLK - 64) * 4 + local;
    ms[local][j] = PE[d * 64 + j];
    __syncthreads();
    float ag = bg[j], ab = bb[j];
    #pragma unroll
    for (int k = 0; k < 64; k++) {
        float m = ms[local][k];
        ag += m * Wg[k * 64 + j];
        ab += m * Wb[k * 64 + j];
    }
    float gam = lrelu(ag), bet = lrelu(ab);
    ((float*)g_gamtab4)[d * 64 + j] = gam;
    ((float*)g_bettab4)[d * 64 + j] = bet;
    float pg = gam * gam, pb = bet * bet;
    #pragma unroll
    for (int o = 16; o; o >>= 1) {
        pg += __shfl_down_sync(0xFFFFFFFFu, pg, o);
        pb += __shfl_down_sync(0xFFFFFFFFu, pb, o);
    }
    int w = tid >> 5;
    if ((tid & 31) == 0) { pG[w] = pg; pB[w] = pb; }
    __syncthreads();
    if (j == 0) {
        g_ngamtab[d] = sqrtf(pG[2 * local] + pG[2 * local + 1]);
        g_nbettab[d] = sqrtf(pB[2 * local] + pB[2 * local + 1]);
    }
}

// ---------------- S1: per-block sums + degsum reduction ----------------------
__global__ void k_scan1() {
    __shared__ int ws[8];
    int tid = threadIdx.x;
    int lane = tid & 31, w = tid >> 5;
    if (blockIdx.x == NBLK) {
        int v = (tid < NBLK) ? g_dpart[tid] : 0;
        #pragma unroll
        for (int o = 16; o; o >>= 1) v += __shfl_down_sync(0xFFFFFFFFu, v, o);
        if (lane == 0) ws[w] = v;
        __syncthreads();
        if (tid == 0) {
            int s = 0;
            #pragma unroll
            for (int q = 0; q < 8; q++) s += ws[q];
            g_Kthr = (float)((double)s / (double)Nn);
        }
        return;
    }
    int i = blockIdx.x * 256 + tid;
    int v = (i < Nn) ? g_cnt[i] : 0;
    int s = v;
    #pragma unroll
    for (int o = 16; o; o >>= 1) s += __shfl_down_sync(0xFFFFFFFFu, s, o);
    if (lane == 0) ws[w] = s;
    __syncthreads();
    if (tid == 0) {
        int t = 0;
        #pragma unroll
        for (int q = 0; q < 8; q++) t += ws[q];
        g_bsum[blockIdx.x] = t;
    }
}

// ---------------- S3: replicated block-sum scan + local scan + cnt re-zero ---
__global__ void k_scan3b() {
    __shared__ int ws[8];
    __shared__ int base_s, tot_s;
    int tid = threadIdx.x;
    int lane = tid & 31, w = tid >> 5;
    {
        int v = (tid < NBLK) ? g_bsum[tid] : 0;
        int orig = v;
        #pragma unroll
        for (int o = 1; o < 32; o <<= 1) { int u = __shfl_up_sync(0xFFFFFFFFu, v, o); if (lane >= o) v += u; }
        if (lane == 31) ws[w] = v;
        __syncthreads();
        if (w == 0 && lane < 8) {
            int u = ws[lane];
            #pragma unroll
            for (int o = 1; o < 8; o <<= 1) { int z = __shfl_up_sync(0xFFu, u, o); if (lane >= o) u += z; }
            ws[lane] = u;
        }
        __syncthreads();
        int incl = v + (w ? ws[w - 1] : 0);
        if (tid == (int)blockIdx.x) base_s = incl - orig;
        if (tid == NBLK - 1) tot_s = incl;
        __syncthreads();
    }
    int i = blockIdx.x * 256 + tid;
    int c = (i < Nn) ? g_cnt[i] : 0;
    int corig = c;
    #pragma unroll
    for (int o = 1; o < 32; o <<= 1) { int u = __shfl_up_sync(0xFFFFFFFFu, c, o); if (lane >= o) c += u; }
    if (lane == 31) ws[w] = c;
    __syncthreads();
    if (w == 0 && lane < 8) {
        int u = ws[lane];
        #pragma unroll
        for (int o = 1; o < 8; o <<= 1) { int z = __shfl_up_sync(0xFFu, u, o); if (lane >= o) u += z; }
        ws[lane] = u;
    }
    __syncthreads();
    int excl = c - corig + (w ? ws[w - 1] : 0) + base_s;
    if (i < Nn) {
        g_off[i] = excl; g_cur[i] = excl;
        g_cnt[i] = 0;
    }
    if (blockIdx.x == 0 && tid == 0) g_off[Nn] = tot_s;
}

// ---------------- SH: scatter (int4) co-scheduled with h-GEMM (64 nodes/blk) -
#define SH_SMEM 65536
__global__ void __launch_bounds__(256) k_sh(const int* __restrict__ edge,
                                            const float* __restrict__ x,
                                            const float* __restrict__ b,
                                            const float* __restrict__ a) {
    extern __shared__ float4 sh4[];
    float4* Ws = sh4;            // 128*16 float4 = 32KB
    float4* xs = sh4 + 2048;     // 64*32  float4 = 32KB
    if (blockIdx.x < SBLK) {          // -------- scatter branch --------
        int t = blockIdx.x * 256 + threadIdx.x;
        if (t < Ee / 4) {
            int4 s4 = ((const int4*)edge)[t];
            int4 d4 = ((const int4*)(edge + Ee))[t];
            int p;
            p = atomicAdd(&g_cur[s4.x], 1); g_dsts[p] = d4.x;
            p = atomicAdd(&g_cur[s4.y], 1); g_dsts[p] = d4.y;
            p = atomicAdd(&g_cur[s4.z], 1); g_dsts[p] = d4.z;
            p = atomicAdd(&g_cur[s4.w], 1); g_dsts[p] = d4.w;
        }
        return;
    }
    // -------- h = (xW^T+b)*8 ; s,t projections : 64 nodes, 4 per thread ------
    int tid = threadIdx.x;
    const float4* Wt4 = (const float4*)g_Wt;
    for (int p = tid; p < 2048; p += 256) Ws[p] = Wt4[p];
    int n0 = (blockIdx.x - SBLK) * 64;
    const float4* x4 = (const float4*)x;
    for (int p = tid; p < 2048; p += 256) {
        int n = p >> 5, kq = p & 31;
        int node = n0 + n;
        xs[p] = (node < Nn) ? x4[node * 32 + kq] : make_float4(0.f, 0.f, 0.f, 0.f);
    }
    __syncthreads();

    int og = tid & 15, ng = tid >> 4;       // 16 output-groups x 16 node-groups
    int nbase = 4 * ng;
    float4 acc0 = make_float4(0.f, 0.f, 0.f, 0.f);
    float4 acc1 = acc0, acc2 = acc0, acc3 = acc0;
    #pragma unroll 4
    for (int kq = 0; kq < 32; kq++) {
        float4 w0 = Ws[(4 * kq + 0) * 16 + og];
        float4 w1 = Ws[(4 * kq + 1) * 16 + og];
        float4 w2 = Ws[(4 * kq + 2) * 16 + og];
        float4 w3 = Ws[(4 * kq + 3) * 16 + og];
        float4 x0 = xs[(nbase + 0) * 32 + kq];
        float4 x1 = xs[(nbase + 1) * 32 + kq];
        float4 x2 = xs[(nbase + 2) * 32 + kq];
        float4 x3 = xs[(nbase + 3) * 32 + kq];
        acc0.x += x0.x * w0.x + x0.y * w1.x + x0.z * w2.x + x0.w * w3.x;
        acc0.y += x0.x * w0.y + x0.y * w1.y + x0.z * w2.y + x0.w * w3.y;
        acc0.z += x0.x * w0.z + x0.y * w1.z + x0.z * w2.z + x0.w * w3.z;
        acc0.w += x0.x * w0.w + x0.y * w1.w + x0.z * w2.w + x0.w * w3.w;
        acc1.x += x1.x * w0.x + x1.y * w1.x + x1.z * w2.x + x1.w * w3.x;
        acc1.y += x1.x * w0.y + x1.y * w1.y + x1.z * w2.y + x1.w * w3.y;
        acc1.z += x1.x * w0.z + x1.y * w1.z + x1.z * w2.z + x1.w * w3.z;
        acc1.w += x1.x * w0.w + x1.y * w1.w + x1.z * w2.w + x1.w * w3.w;
        acc2.x += x2.x * w0.x + x2.y * w1.x + x2.z * w2.x + x2.w * w3.x;
        acc2.y += x2.x * w0.y + x2.y * w1.y + x2.z * w2.y + x2.w * w3.y;
        acc2.z += x2.x * w0.z + x2.y * w1.z + x2.z * w2.z + x2.w * w3.z;
        acc2.w += x2.x * w0.w + x2.y * w1.w + x2.z * w2.w + x2.w * w3.w;
        acc3.x += x3.x * w0.x + x3.y * w1.x + x3.z * w2.x + x3.w * w3.x;
        acc3.y += x3.x * w0.y + x3.y * w1.y + x3.z * w2.y + x3.w * w3.y;
        acc3.z += x3.x * w0.z + x3.y * w1.z + x3.z * w2.z + x3.w * w3.z;
        acc3.w += x3.x * w0.w + x3.y * w1.w + x3.z * w2.w + x3.w * w3.w;
    }
    float4 b4  = ((const float4*)b)[og];
    float4 as4 = ((const float4*)a)[og];
    float4 at4 = ((const float4*)a)[16 + og];
    #pragma unroll
    for (int i = 0; i < 4; i++) {
        float4 A = (i == 0) ? acc0 : (i == 1) ? acc1 : (i == 2) ? acc2 : acc3;
        float4 h = make_float4((A.x + b4.x) * 8.f, (A.y + b4.y) * 8.f,
                               (A.z + b4.z) * 8.f, (A.w + b4.w) * 8.f);
        int node = n0 + nbase + i;
        if (node < Nn) g_h4[node * 16 + og] = h;
        float sv = h.x * as4.x + h.y * as4.y + h.z * as4.z + h.w * as4.w;
        float tv = h.x * at4.x + h.y * at4.y + h.z * at4.z + h.w * at4.w;
        #pragma unroll
        for (int o = 8; o; o >>= 1) {
            sv += __shfl_down_sync(0xFFFFFFFFu, sv, o, 16);
            tv += __shfl_down_sync(0xFFFFFFFFu, tv, o, 16);
        }
        if (og == 0 && node < Nn) { g_s[node] = sv; g_t[node] = tv; }
    }
}

// ---------------- GF: fused gather (half-warp/edge, float4) + epilogue -------
#define GF_SMEM 49536
__global__ void __launch_bounds__(256) k_gf(const int* __restrict__ degree,
                                            float* __restrict__ out) {
    extern __shared__ float sm[];
    float4* WsA  = (float4*)sm;
    float4* WsR  = WsA + 1024;
    float*  sAgg = sm + 8192;
    float*  sHp  = sAgg + 2048;
    float*  sRs  = sHp + 2048;
    float*  sInv = sRs + 32;
    int*    sDeg = (int*)(sInv + 32);
    int tid = threadIdx.x;
    const float4* Wa4 = (const float4*)g_WaT;
    const float4* Wr4 = (const float4*)g_WrT;
    for (int p = tid; p < 1024; p += 256) { WsA[p] = Wa4[p]; WsR[p] = Wr4[p]; }
    int n0 = blockIdx.x * 32;
    if (tid < 32) {
        int node = n0 + tid;
        int d = (node < Nn) ? degree[node] : 1;
        sDeg[tid] = d;
        sInv[tid] = (d == 0) ? 0.f : 1.f / (float)d;
    }
    int w = tid >> 5, lane = tid & 31;
    int lq = lane & 15, half = lane >> 4;
    const float4* h4 = (const float4*)g_h4;
    #pragma unroll
    for (int k = 0; k < 4; k++) {
        int nl = w + 8 * k;
        int node = n0 + nl;
        float4 acc  = make_float4(0.f, 0.f, 0.f, 0.f);
        float4 wacc = acc;
        float rs = 0.f;
        if (node < Nn) {
            int s0 = g_off[node], s1 = g_off[node + 1];
            float ssrc = g_s[node];
            for (int base = s0; base < s1; base += 32) {
                int m = s1 - base; if (m > 32) m = 32;
                int dst = 0; float ev = 0.f;
                if (lane < m) {
                    dst = g_dsts[base + lane];
                    float z = ssrc + g_t[dst];
                    ev = __expf(-(z > 0.f ? z : 0.01f * z));
                    rs += ev;
                }
                if (m == 32) {
                    #pragma unroll 8
                    for (int p = 0; p < 16; p++) {
                        int j = 2 * p + half;
                        int  dd = __shfl_sync(0xFFFFFFFFu, dst, j);
                        float e = __shfl_sync(0xFFFFFFFFu, ev, j);
                        float4 v = h4[dd * 16 + lq];
                        acc.x += v.x;  acc.y += v.y;  acc.z += v.z;  acc.w += v.w;
                        wacc.x += e * v.x; wacc.y += e * v.y;
                        wacc.z += e * v.z; wacc.w += e * v.w;
                    }
                } else {
                    // uniform trip count across the whole warp; clamp shfl src,
                    // predicate the accumulate (fixes divergent-shfl UB)
                    int pm = (m + 1) >> 1;
                    for (int p = 0; p < pm; p++) {
                        int j = 2 * p + half;
                        int jj = (j < m) ? j : 0;
                        int  dd = __shfl_sync(0xFFFFFFFFu, dst, jj);
                        float e = __shfl_sync(0xFFFFFFFFu, ev, jj);
                        if (j < m) {
                            float4 v = h4[dd * 16 + lq];
                            acc.x += v.x;  acc.y += v.y;  acc.z += v.z;  acc.w += v.w;
                            wacc.x += e * v.x; wacc.y += e * v.y;
                            wacc.z += e * v.z; wacc.w += e * v.w;
                        }
                    }
                }
            }
        }
        // combine the two half-warps
        acc.x  += __shfl_down_sync(0xFFFFFFFFu, acc.x, 16);
        acc.y  += __shfl_down_sync(0xFFFFFFFFu, acc.y, 16);
        acc.z  += __shfl_down_sync(0xFFFFFFFFu, acc.z, 16);
        acc.w  += __shfl_down_sync(0xFFFFFFFFu, acc.w, 16);
        wacc.x += __shfl_down_sync(0xFFFFFFFFu, wacc.x, 16);
        wacc.y += __shfl_down_sync(0xFFFFFFFFu, wacc.y, 16);
        wacc.z += __shfl_down_sync(0xFFFFFFFFu, wacc.z, 16);
        wacc.w += __shfl_down_sync(0xFFFFFFFFu, wacc.w, 16);
        if (lane < 16) {
            ((float4*)sAgg)[nl * 16 + lq] = acc;
            ((float4*)sHp)[nl * 16 + lq]  = wacc;
        }
        #pragma unroll
        for (int o = 16; o; o >>= 1) rs += __shfl_down_sync(0xFFFFFFFFu, rs, o);
        if (lane == 0) sRs[nl] = rs;
    }
    __syncthreads();
    for (int p = tid; p < 2048; p += 256) sAgg[p] *= sInv[p >> 6];
    __syncthreads();

    int og = tid & 15, ng = tid >> 4;
    int na = 2 * ng, nb = na + 1;
    const float4* is4 = (const float4*)sAgg;
    float4 Aa = make_float4(0.f, 0.f, 0.f, 0.f), Ra = Aa, Ab = Aa, Rb = Aa;
    #pragma unroll 4
    for (int kq = 0; kq < 16; kq++) {
        float4 xa = is4[na * 16 + kq];
        float4 xb = is4[nb * 16 + kq];
        #pragma unroll
        for (int r = 0; r < 4; r++) {
            float4 wa = WsA[(4 * kq + r) * 16 + og];
            float4 wr = WsR[(4 * kq + r) * 16 + og];
            float xav = (r == 0) ? xa.x : (r == 1) ? xa.y : (r == 2) ? xa.z : xa.w;
            float xbv = (r == 0) ? xb.x : (r == 1) ? xb.y : (r == 2) ? xb.z : xb.w;
            Aa.x += xav * wa.x; Aa.y += xav * wa.y; Aa.z += xav * wa.z; Aa.w += xav * wa.w;
            Ra.x += xav * wr.x; Ra.y += xav * wr.y; Ra.z += xav * wr.z; Ra.w += xav * wr.w;
            Ab.x += xbv * wa.x; Ab.y += xbv * wa.y; Ab.z += xbv * wa.z; Ab.w += xbv * wa.w;
            Rb.x += xbv * wr.x; Rb.y += xbv * wr.y; Rb.z += xbv * wr.z; Rb.w += xbv * wr.w;
        }
    }
    float Kthr = g_Kthr;

    #pragma unroll
    for (int hh = 0; hh < 2; hh++) {
        int nl = hh ? nb : na;
        int node = n0 + nl;
        float4 Av = hh ? Ab : Aa;
        float4 Rv = hh ? Rb : Ra;
        float pa = 0.f, pr = 0.f;
        float4 o4 = make_float4(0.f, 0.f, 0.f, 0.f);
        if (node < Nn) {
            int d = sDeg[nl];
            float4 gam = g_gamtab4[d * 16 + og];
            float4 bet = g_bettab4[d * 16 + og];
            float4 ba, br;
            ba.x = (gam.x + 1.f) * Av.x + bet.x;  br.x = (gam.x + 1.f) * Rv.x + bet.x;
            ba.y = (gam.y + 1.f) * Av.y + bet.y;  br.y = (gam.y + 1.f) * Rv.y + bet.y;
            ba.z = (gam.z + 1.f) * Av.z + bet.z;  br.z = (gam.z + 1.f) * Rv.z + bet.z;
            ba.w = (gam.w + 1.f) * Av.w + bet.w;  br.w = (gam.w + 1.f) * Rv.w + bet.w;
            float R = ((float)d < Kthr) ? 1.f : 0.f;
            const float4* hp4 = (const float4*)sHp;
            float4 hp = hp4[nl * 16 + og];
            float inv = 1.f / (sRs[nl] + 1e-5f + 1.f);
            float bx = 0.1f * (R * ba.x - (1.f - R) * br.x);
            float by = 0.1f * (R * ba.y - (1.f - R) * br.y);
            float bz = 0.1f * (R * ba.z - (1.f - R) * br.z);
            float bw = 0.1f * (R * ba.w - (1.f - R) * br.w);
            o4.x = lrelu((hp.x + bx) * inv);
            o4.y = lrelu((hp.y + by) * inv);
            o4.z = lrelu((hp.z + bz) * inv);
            o4.w = lrelu((hp.w + bw) * inv);
            pa = ba.x * ba.x + ba.y * ba.y + ba.z * ba.z + ba.w * ba.w;
            pr = br.x * br.x + br.y * br.y + br.z * br.z + br.w * br.w;
        }
        #pragma unroll
        for (int o = 8; o; o >>= 1) {
            pa += __shfl_down_sync(0xFFFFFFFFu, pa, o, 16);
            pr += __shfl_down_sync(0xFFFFFFFFu, pr, o, 16);
        }
        if (node < Nn) {
            ((float4*)out)[node * 16 + og] = o4;
            if (og == 0) { g_nadd[node] = sqrtf(pa); g_nrev[node] = sqrtf(pr); }
        }
    }
}

// ---------------- L: loss reductions over idx -------------------------------
__global__ void k_loss(const int* __restrict__ degree, const int* __restrict__ idx,
                       float* __restrict__ out) {
    __shared__ float sb[256], sf[256];
    float Kthr = g_Kthr;
    float lb = 0.f, lf = 0.f;
    for (int i = threadIdx.x; i < NIDX; i += 256) {
        int r = idx[i];
        int d = degree[r];
        bool R = ((float)d) < Kthr;
        lb += R ? g_nadd[r] : g_nrev[r];
        lf += g_ngamtab[d] + g_nbettab[d];
    }
    sb[threadIdx.x] = lb; sf[threadIdx.x] = lf;
    __syncthreads();
    for (int s = 128; s; s >>= 1) {
        if (threadIdx.x < (unsigned)s) {
            sb[threadIdx.x] += sb[threadIdx.x + s];
            sf[threadIdx.x] += sf[threadIdx.x + s];
        }
        __syncthreads();
    }
    if (threadIdx.x == 0) {
        out[Nn * OUTF]     = sb[0] / (float)NIDX;
        out[Nn * OUTF + 1] = sf[0] / (float)NIDX;
    }
}

// ---------------- launch -----------------------------------------------------
extern "C" void kernel_launch(void* const* d_in, const int* in_sizes, int n_in,
                              void* d_out, int out_size) {
    const float* x      = (const float*)d_in[0];
    const float* W      = (const float*)d_in[1];
    const float* b      = (const float*)d_in[2];
    const float* a      = (const float*)d_in[3];
    const float* Wg     = (const float*)d_in[4];
    const float* Wb     = (const float*)d_in[5];
    const float* bg     = (const float*)d_in[6];
    const float* bb     = (const float*)d_in[7];
    const float* Wadd   = (const float*)d_in[8];
    const float* Wrev   = (const float*)d_in[9];
    const float* PE     = (const float*)d_in[10];
    const int*   edge   = (const int*)d_in[11];
    const int*   degree = (const int*)d_in[12];
    const int*   idx    = (const int*)d_in[13];
    float* out = (float*)d_out;

    cudaFuncSetAttribute(k_sh, cudaFuncAttributeMaxDynamicSharedMemorySize, SH_SMEM);
    cudaFuncSetAttribute(k_gf, cudaFuncAttributeMaxDynamicSharedMemorySize, GF_SMEM);

    k_ph<<<SBLK + NBLK + 64 + 64, 256>>>(edge, degree, W, Wadd, Wrev, Wg, Wb, bg, bb, PE);
    k_scan1<<<NBLK + 1, 256>>>();
    k_scan3b<<<NBLK, 256>>>();
    k_sh<<<SBLK + HBLK2, 256, SH_SMEM>>>(edge, x, b, a);
    k_gf<<<GBLK, 256, GF_SMEM>>>(degree, out);
    if (out_size >= Nn * OUTF + 2)
        k_loss<<<1, 256>>>(degree, idx, out);
}

// round 13
// speedup vs baseline: 1.1562x; 1.0104x over previous
#include <cuda_runtime.h>
#include <math.h>

#define Nn   50000
#define Ee   1600000
#define INF  128
#define OUTF 64
#define NIDX 5000
#define NBLK 196        // ceil(Nn/256)
#define HBLK2 782       // ceil(Nn/64)
#define GBLK 1563       // ceil(Nn/32)
#define SBLK 1563       // ceil(Ee/4/256)

// ---------------- scratch (device globals) ----------------------------------
__device__ float4 g_h4[Nn * 16];
__device__ float  g_s[Nn];
__device__ float  g_t[Nn];
__device__ float  g_nadd[Nn];
__device__ float  g_nrev[Nn];
__device__ float4 g_gamtab4[256 * 16];
__device__ float4 g_bettab4[256 * 16];
__device__ float  g_ngamtab[256];
__device__ float  g_nbettab[256];
__device__ float  g_Wt[INF * OUTF];
__device__ float  g_WaT[OUTF * OUTF];
__device__ float  g_WrT[OUTF * OUTF];
__device__ int    g_cnt[Nn];          // zero at module load; re-zeroed by k_scan3b
__device__ int    g_off[Nn + 1];
__device__ int    g_cur[Nn];
__device__ int    g_dsts[Ee];
__device__ int    g_bsum[NBLK];
__device__ int    g_dpart[NBLK];
__device__ float  g_Kthr;

__device__ __forceinline__ float lrelu(float v) { return v > 0.f ? v : 0.01f * v; }

// ---------------- PH: hist + degree partials + transposes + gbtab -----------
__global__ void k_ph(const int* __restrict__ edge, const int* __restrict__ degree,
                     const float* __restrict__ W, const float* __restrict__ Wa,
                     const float* __restrict__ Wr, const float* __restrict__ Wg_,
                     const float* __restrict__ Wb_, const float* __restrict__ bg,
                     const float* __restrict__ bb, const float* __restrict__ PE) {
    int blk = blockIdx.x, tid = threadIdx.x;
    if (blk < SBLK) {                             // ---- edge histogram (int4) ----
        int t = blk * 256 + tid;
        if (t < Ee / 4) {
            int4 e = ((const int4*)edge)[t];
            atomicAdd(&g_cnt[e.x], 1);
            atomicAdd(&g_cnt[e.y], 1);
            atomicAdd(&g_cnt[e.z], 1);
            atomicAdd(&g_cnt[e.w], 1);
        }
        return;
    }
    if (blk < SBLK + NBLK) {                      // ---- degree partial sums ----
        __shared__ int ws[8];
        int bb2 = blk - SBLK;
        int t = bb2 * 256 + tid;
        int d = (t < Nn) ? degree[t] : 0;
        #pragma unroll
        for (int o = 16; o; o >>= 1) d += __shfl_down_sync(0xFFFFFFFFu, d, o);
        int lane = tid & 31, w = tid >> 5;
        if (lane == 0) ws[w] = d;
        __syncthreads();
        if (tid == 0) {
            int s = 0;
            #pragma unroll
            for (int q = 0; q < 8; q++) s += ws[q];
            g_dpart[bb2] = s;
        }
        return;
    }
    if (blk < SBLK + NBLK + 64) {                 // ---- weight transposes ----
        int t = (blk - SBLK - NBLK) * 256 + tid;
        if (t < 8192) {
            int k = t >> 6, j = t & 63;
            g_Wt[t] = W[j * 128 + k];
        } else if (t < 12288) {
            int p = t - 8192; int k = p >> 6, j = p & 63;
            g_WaT[p] = Wa[j * 64 + k];
        } else {
            int p = t - 12288; int k = p >> 6, j = p & 63;
            g_WrT[p] = Wr[j * 64 + k];
        }
        return;
    }
    // ---- gamma/beta tables over 256 degrees ----
    __shared__ float Wg[4096], Wb[4096];
    __shared__ float ms[4][64];
    __shared__ float pG[8], pB[8];
    for (int p = tid; p < 4096; p += 256) { Wg[p] = Wg_[p]; Wb[p] = Wb_[p]; }
    int local = tid >> 6, j = tid & 63;
    int d = (blk - SBLK - NBLK - 64) * 4 + local;
    ms[local][j] = PE[d * 64 + j];
    __syncthreads();
    float ag = bg[j], ab = bb[j];
    #pragma unroll
    for (int k = 0; k < 64; k++) {
        float m = ms[local][k];
        ag += m * Wg[k * 64 + j];
        ab += m * Wb[k * 64 + j];
    }
    float gam = lrelu(ag), bet = lrelu(ab);
    ((float*)g_gamtab4)[d * 64 + j] = gam;
    ((float*)g_bettab4)[d * 64 + j] = bet;
    float pg = gam * gam, pb = bet * bet;
    #pragma unroll
    for (int o = 16; o; o >>= 1) {
        pg += __shfl_down_sync(0xFFFFFFFFu, pg, o);
        pb += __shfl_down_sync(0xFFFFFFFFu, pb, o);
    }
    int w = tid >> 5;
    if ((tid & 31) == 0) { pG[w] = pg; pB[w] = pb; }
    __syncthreads();
    if (j == 0) {
        g_ngamtab[d] = sqrtf(pG[2 * local] + pG[2 * local + 1]);
        g_nbettab[d] = sqrtf(pB[2 * local] + pB[2 * local + 1]);
    }
}

// ---------------- S1: per-block sums + degsum reduction ----------------------
__global__ void k_scan1() {
    __shared__ int ws[8];
    int tid = threadIdx.x;
    int lane = tid & 31, w = tid >> 5;
    if (blockIdx.x == NBLK) {
        int v = (tid < NBLK) ? g_dpart[tid] : 0;
        #pragma unroll
        for (int o = 16; o; o >>= 1) v += __shfl_down_sync(0xFFFFFFFFu, v, o);
        if (lane == 0) ws[w] = v;
        __syncthreads();
        if (tid == 0) {
            int s = 0;
            #pragma unroll
            for (int q = 0; q < 8; q++) s += ws[q];
            g_Kthr = (float)((double)s / (double)Nn);
        }
        return;
    }
    int i = blockIdx.x * 256 + tid;
    int v = (i < Nn) ? g_cnt[i] : 0;
    int s = v;
    #pragma unroll
    for (int o = 16; o; o >>= 1) s += __shfl_down_sync(0xFFFFFFFFu, s, o);
    if (lane == 0) ws[w] = s;
    __syncthreads();
    if (tid == 0) {
        int t = 0;
        #pragma unroll
        for (int q = 0; q < 8; q++) t += ws[q];
        g_bsum[blockIdx.x] = t;
    }
}

// ---------------- S3: replicated block-sum scan + local scan + cnt re-zero ---
__global__ void k_scan3b() {
    __shared__ int ws[8];
    __shared__ int base_s, tot_s;
    int tid = threadIdx.x;
    int lane = tid & 31, w = tid >> 5;
    {
        int v = (tid < NBLK) ? g_bsum[tid] : 0;
        int orig = v;
        #pragma unroll
        for (int o = 1; o < 32; o <<= 1) { int u = __shfl_up_sync(0xFFFFFFFFu, v, o); if (lane >= o) v += u; }
        if (lane == 31) ws[w] = v;
        __syncthreads();
        if (w == 0 && lane < 8) {
            int u = ws[lane];
            #pragma unroll
            for (int o = 1; o < 8; o <<= 1) { int z = __shfl_up_sync(0xFFu, u, o); if (lane >= o) u += z; }
            ws[lane] = u;
        }
        __syncthreads();
        int incl = v + (w ? ws[w - 1] : 0);
        if (tid == (int)blockIdx.x) base_s = incl - orig;
        if (tid == NBLK - 1) tot_s = incl;
        __syncthreads();
    }
    int i = blockIdx.x * 256 + tid;
    int c = (i < Nn) ? g_cnt[i] : 0;
    int corig = c;
    #pragma unroll
    for (int o = 1; o < 32; o <<= 1) { int u = __shfl_up_sync(0xFFFFFFFFu, c, o); if (lane >= o) c += u; }
    if (lane == 31) ws[w] = c;
    __syncthreads();
    if (w == 0 && lane < 8) {
        int u = ws[lane];
        #pragma unroll
        for (int o = 1; o < 8; o <<= 1) { int z = __shfl_up_sync(0xFFu, u, o); if (lane >= o) u += z; }
        ws[lane] = u;
    }
    __syncthreads();
    int excl = c - corig + (w ? ws[w - 1] : 0) + base_s;
    if (i < Nn) {
        g_off[i] = excl; g_cur[i] = excl;
        g_cnt[i] = 0;
    }
    if (blockIdx.x == 0 && tid == 0) g_off[Nn] = tot_s;
}

// ---------------- SH: scatter (int4) co-scheduled with h-GEMM (64 nodes/blk) -
// smem = 32KB (Ws) + 16KB (xs half-buffer) = 48KB -> 4 blocks/SM
#define SH_SMEM 49152
__global__ void __launch_bounds__(256) k_sh(const int* __restrict__ edge,
                                            const float* __restrict__ x,
                                            const float* __restrict__ b,
                                            const float* __restrict__ a) {
    extern __shared__ float4 sh4[];
    float4* Ws = sh4;            // 128*16 float4 = 32KB
    float4* xs = sh4 + 2048;     // 64 nodes * 16 kq float4 = 16KB (reused 2x)
    if (blockIdx.x < SBLK) {          // -------- scatter branch --------
        int t = blockIdx.x * 256 + threadIdx.x;
        if (t < Ee / 4) {
            int4 s4 = ((const int4*)edge)[t];
            int4 d4 = ((const int4*)(edge + Ee))[t];
            int p;
            p = atomicAdd(&g_cur[s4.x], 1); g_dsts[p] = d4.x;
            p = atomicAdd(&g_cur[s4.y], 1); g_dsts[p] = d4.y;
            p = atomicAdd(&g_cur[s4.z], 1); g_dsts[p] = d4.z;
            p = atomicAdd(&g_cur[s4.w], 1); g_dsts[p] = d4.w;
        }
        return;
    }
    // -------- h = (xW^T+b)*8 ; s,t projections : 64 nodes, 4 per thread ------
    int tid = threadIdx.x;
    const float4* Wt4 = (const float4*)g_Wt;
    for (int p = tid; p < 2048; p += 256) Ws[p] = Wt4[p];
    int n0 = (blockIdx.x - SBLK) * 64;
    const float4* x4 = (const float4*)x;

    int og = tid & 15, ng = tid >> 4;       // 16 output-groups x 16 node-groups
    int nbase = 4 * ng;
    float4 acc0 = make_float4(0.f, 0.f, 0.f, 0.f);
    float4 acc1 = acc0, acc2 = acc0, acc3 = acc0;

    #pragma unroll
    for (int hf = 0; hf < 2; hf++) {
        __syncthreads();   // first iter: covers Ws staging; later: xs reuse
        for (int p = tid; p < 1024; p += 256) {
            int n = p >> 4, kq = p & 15;
            int node = n0 + n;
            xs[p] = (node < Nn) ? x4[node * 32 + hf * 16 + kq]
                                : make_float4(0.f, 0.f, 0.f, 0.f);
        }
        __syncthreads();
        #pragma unroll 4
        for (int kq = 0; kq < 16; kq++) {
            int kg = hf * 16 + kq;
            float4 w0 = Ws[(4 * kg + 0) * 16 + og];
            float4 w1 = Ws[(4 * kg + 1) * 16 + og];
            float4 w2 = Ws[(4 * kg + 2) * 16 + og];
            float4 w3 = Ws[(4 * kg + 3) * 16 + og];
            float4 x0 = xs[(nbase + 0) * 16 + kq];
            float4 x1 = xs[(nbase + 1) * 16 + kq];
            float4 x2 = xs[(nbase + 2) * 16 + kq];
            float4 x3 = xs[(nbase + 3) * 16 + kq];
            acc0.x += x0.x * w0.x + x0.y * w1.x + x0.z * w2.x + x0.w * w3.x;
            acc0.y += x0.x * w0.y + x0.y * w1.y + x0.z * w2.y + x0.w * w3.y;
            acc0.z += x0.x * w0.z + x0.y * w1.z + x0.z * w2.z + x0.w * w3.z;
            acc0.w += x0.x * w0.w + x0.y * w1.w + x0.z * w2.w + x0.w * w3.w;
            acc1.x += x1.x * w0.x + x1.y * w1.x + x1.z * w2.x + x1.w * w3.x;
            acc1.y += x1.x * w0.y + x1.y * w1.y + x1.z * w2.y + x1.w * w3.y;
            acc1.z += x1.x * w0.z + x1.y * w1.z + x1.z * w2.z + x1.w * w3.z;
            acc1.w += x1.x * w0.w + x1.y * w1.w + x1.z * w2.w + x1.w * w3.w;
            acc2.x += x2.x * w0.x + x2.y * w1.x + x2.z * w2.x + x2.w * w3.x;
            acc2.y += x2.x * w0.y + x2.y * w1.y + x2.z * w2.y + x2.w * w3.y;
            acc2.z += x2.x * w0.z + x2.y * w1.z + x2.z * w2.z + x2.w * w3.z;
            acc2.w += x2.x * w0.w + x2.y * w1.w + x2.z * w2.w + x2.w * w3.w;
            acc3.x += x3.x * w0.x + x3.y * w1.x + x3.z * w2.x + x3.w * w3.x;
            acc3.y += x3.x * w0.y + x3.y * w1.y + x3.z * w2.y + x3.w * w3.y;
            acc3.z += x3.x * w0.z + x3.y * w1.z + x3.z * w2.z + x3.w * w3.z;
            acc3.w += x3.x * w0.w + x3.y * w1.w + x3.z * w2.w + x3.w * w3.w;
        }
    }
    float4 b4  = ((const float4*)b)[og];
    float4 as4 = ((const float4*)a)[og];
    float4 at4 = ((const float4*)a)[16 + og];
    #pragma unroll
    for (int i = 0; i < 4; i++) {
        float4 A = (i == 0) ? acc0 : (i == 1) ? acc1 : (i == 2) ? acc2 : acc3;
        float4 h = make_float4((A.x + b4.x) * 8.f, (A.y + b4.y) * 8.f,
                               (A.z + b4.z) * 8.f, (A.w + b4.w) * 8.f);
        int node = n0 + nbase + i;
        if (node < Nn) g_h4[node * 16 + og] = h;
        float sv = h.x * as4.x + h.y * as4.y + h.z * as4.z + h.w * as4.w;
        float tv = h.x * at4.x + h.y * at4.y + h.z * at4.z + h.w * at4.w;
        #pragma unroll
        for (int o = 8; o; o >>= 1) {
            sv += __shfl_down_sync(0xFFFFFFFFu, sv, o, 16);
            tv += __shfl_down_sync(0xFFFFFFFFu, tv, o, 16);
        }
        if (og == 0 && node < Nn) { g_s[node] = sv; g_t[node] = tv; }
    }
}

// ---------------- GF: fused gather (half-warp/edge, float4) + epilogue -------
#define GF_SMEM 49536
__global__ void __launch_bounds__(256) k_gf(const int* __restrict__ degree,
                                            float* __restrict__ out) {
    extern __shared__ float sm[];
    float4* WsA  = (float4*)sm;
    float4* WsR  = WsA + 1024;
    float*  sAgg = sm + 8192;
    float*  sHp  = sAgg + 2048;
    float*  sRs  = sHp + 2048;
    float*  sInv = sRs + 32;
    int*    sDeg = (int*)(sInv + 32);
    int tid = threadIdx.x;
    const float4* Wa4 = (const float4*)g_WaT;
    const float4* Wr4 = (const float4*)g_WrT;
    for (int p = tid; p < 1024; p += 256) { WsA[p] = Wa4[p]; WsR[p] = Wr4[p]; }
    int n0 = blockIdx.x * 32;
    if (tid < 32) {
        int node = n0 + tid;
        int d = (node < Nn) ? degree[node] : 1;
        sDeg[tid] = d;
        sInv[tid] = (d == 0) ? 0.f : 1.f / (float)d;
    }
    int w = tid >> 5, lane = tid & 31;
    int lq = lane & 15, half = lane >> 4;
    const float4* h4 = (const float4*)g_h4;
    #pragma unroll
    for (int k = 0; k < 4; k++) {
        int nl = w + 8 * k;
        int node = n0 + nl;
        float4 acc  = make_float4(0.f, 0.f, 0.f, 0.f);
        float4 wacc = acc;
        float rs = 0.f;
        if (node < Nn) {
            int s0 = g_off[node], s1 = g_off[node + 1];
            float ssrc = g_s[node];
            for (int base = s0; base < s1; base += 32) {
                int m = s1 - base; if (m > 32) m = 32;
                int dst = 0; float ev = 0.f;
                if (lane < m) {
                    dst = g_dsts[base + lane];
                    float z = ssrc + g_t[dst];
                    ev = __expf(-(z > 0.f ? z : 0.01f * z));
                    rs += ev;
                }
                if (m == 32) {
                    #pragma unroll 8
                    for (int p = 0; p < 16; p++) {
                        int j = 2 * p + half;
                        int  dd = __shfl_sync(0xFFFFFFFFu, dst, j);
                        float e = __shfl_sync(0xFFFFFFFFu, ev, j);
                        float4 v = h4[dd * 16 + lq];
                        acc.x += v.x;  acc.y += v.y;  acc.z += v.z;  acc.w += v.w;
                        wacc.x += e * v.x; wacc.y += e * v.y;
                        wacc.z += e * v.z; wacc.w += e * v.w;
                    }
                } else {
                    int pm = (m + 1) >> 1;
                    for (int p = 0; p < pm; p++) {
                        int j = 2 * p + half;
                        int jj = (j < m) ? j : 0;
                        int  dd = __shfl_sync(0xFFFFFFFFu, dst, jj);
                        float e = __shfl_sync(0xFFFFFFFFu, ev, jj);
                        if (j < m) {
                            float4 v = h4[dd * 16 + lq];
                            acc.x += v.x;  acc.y += v.y;  acc.z += v.z;  acc.w += v.w;
                            wacc.x += e * v.x; wacc.y += e * v.y;
                            wacc.z += e * v.z; wacc.w += e * v.w;
                        }
                    }
                }
            }
        }
        acc.x  += __shfl_down_sync(0xFFFFFFFFu, acc.x, 16);
        acc.y  += __shfl_down_sync(0xFFFFFFFFu, acc.y, 16);
        acc.z  += __shfl_down_sync(0xFFFFFFFFu, acc.z, 16);
        acc.w  += __shfl_down_sync(0xFFFFFFFFu, acc.w, 16);
        wacc.x += __shfl_down_sync(0xFFFFFFFFu, wacc.x, 16);
        wacc.y += __shfl_down_sync(0xFFFFFFFFu, wacc.y, 16);
        wacc.z += __shfl_down_sync(0xFFFFFFFFu, wacc.z, 16);
        wacc.w += __shfl_down_sync(0xFFFFFFFFu, wacc.w, 16);
        if (lane < 16) {
            ((float4*)sAgg)[nl * 16 + lq] = acc;
            ((float4*)sHp)[nl * 16 + lq]  = wacc;
        }
        #pragma unroll
        for (int o = 16; o; o >>= 1) rs += __shfl_down_sync(0xFFFFFFFFu, rs, o);
        if (lane == 0) sRs[nl] = rs;
    }
    __syncthreads();
    for (int p = tid; p < 2048; p += 256) sAgg[p] *= sInv[p >> 6];
    __syncthreads();

    int og = tid & 15, ng = tid >> 4;
    int na = 2 * ng, nb = na + 1;
    const float4* is4 = (const float4*)sAgg;
    float4 Aa = make_float4(0.f, 0.f, 0.f, 0.f), Ra = Aa, Ab = Aa, Rb = Aa;
    #pragma unroll 4
    for (int kq = 0; kq < 16; kq++) {
        float4 xa = is4[na * 16 + kq];
        float4 xb = is4[nb * 16 + kq];
        #pragma unroll
        for (int r = 0; r < 4; r++) {
            float4 wa = WsA[(4 * kq + r) * 16 + og];
            float4 wr = WsR[(4 * kq + r) * 16 + og];
            float xav = (r == 0) ? xa.x : (r == 1) ? xa.y : (r == 2) ? xa.z : xa.w;
            float xbv = (r == 0) ? xb.x : (r == 1) ? xb.y : (r == 2) ? xb.z : xb.w;
            Aa.x += xav * wa.x; Aa.y += xav * wa.y; Aa.z += xav * wa.z; Aa.w += xav * wa.w;
            Ra.x += xav * wr.x; Ra.y += xav * wr.y; Ra.z += xav * wr.z; Ra.w += xav * wr.w;
            Ab.x += xbv * wa.x; Ab.y += xbv * wa.y; Ab.z += xbv * wa.z; Ab.w += xbv * wa.w;
            Rb.x += xbv * wr.x; Rb.y += xbv * wr.y; Rb.z += xbv * wr.z; Rb.w += xbv * wr.w;
        }
    }
    float Kthr = g_Kthr;

    #pragma unroll
    for (int hh = 0; hh < 2; hh++) {
        int nl = hh ? nb : na;
        int node = n0 + nl;
        float4 Av = hh ? Ab : Aa;
        float4 Rv = hh ? Rb : Ra;
        float pa = 0.f, pr = 0.f;
        float4 o4 = make_float4(0.f, 0.f, 0.f, 0.f);
        if (node < Nn) {
            int d = sDeg[nl];
            float4 gam = g_gamtab4[d * 16 + og];
            float4 bet = g_bettab4[d * 16 + og];
            float4 ba, br;
            ba.x = (gam.x + 1.f) * Av.x + bet.x;  br.x = (gam.x + 1.f) * Rv.x + bet.x;
            ba.y = (gam.y + 1.f) * Av.y + bet.y;  br.y = (gam.y + 1.f) * Rv.y + bet.y;
            ba.z = (gam.z + 1.f) * Av.z + bet.z;  br.z = (gam.z + 1.f) * Rv.z + bet.z;
            ba.w = (gam.w + 1.f) * Av.w + bet.w;  br.w = (gam.w + 1.f) * Rv.w + bet.w;
            float R = ((float)d < Kthr) ? 1.f : 0.f;
            const float4* hp4 = (const float4*)sHp;
            float4 hp = hp4[nl * 16 + og];
            float inv = 1.f / (sRs[nl] + 1e-5f + 1.f);
            float bx = 0.1f * (R * ba.x - (1.f - R) * br.x);
            float by = 0.1f * (R * ba.y - (1.f - R) * br.y);
            float bz = 0.1f * (R * ba.z - (1.f - R) * br.z);
            float bw = 0.1f * (R * ba.w - (1.f - R) * br.w);
            o4.x = lrelu((hp.x + bx) * inv);
            o4.y = lrelu((hp.y + by) * inv);
            o4.z = lrelu((hp.z + bz) * inv);
            o4.w = lrelu((hp.w + bw) * inv);
            pa = ba.x * ba.x + ba.y * ba.y + ba.z * ba.z + ba.w * ba.w;
            pr = br.x * br.x + br.y * br.y + br.z * br.z + br.w * br.w;
        }
        #pragma unroll
        for (int o = 8; o; o >>= 1) {
            pa += __shfl_down_sync(0xFFFFFFFFu, pa, o, 16);
            pr += __shfl_down_sync(0xFFFFFFFFu, pr, o, 16);
        }
        if (node < Nn) {
            ((float4*)out)[node * 16 + og] = o4;
            if (og == 0) { g_nadd[node] = sqrtf(pa); g_nrev[node] = sqrtf(pr); }
        }
    }
}

// ---------------- L: loss reductions over idx -------------------------------
__global__ void k_loss(const int* __restrict__ degree, const int* __restrict__ idx,
                       float* __restrict__ out) {
    __shared__ float sb[256], sf[256];
    float Kthr = g_Kthr;
    float lb = 0.f, lf = 0.f;
    for (int i = threadIdx.x; i < NIDX; i += 256) {
        int r = idx[i];
        int d = degree[r];
        bool R = ((float)d) < Kthr;
        lb += R ? g_nadd[r] : g_nrev[r];
        lf += g_ngamtab[d] + g_nbettab[d];
    }
    sb[threadIdx.x] = lb; sf[threadIdx.x] = lf;
    __syncthreads();
    for (int s = 128; s; s >>= 1) {
        if (threadIdx.x < (unsigned)s) {
            sb[threadIdx.x] += sb[threadIdx.x + s];
            sf[threadIdx.x] += sf[threadIdx.x + s];
        }
        __syncthreads();
    }
    if (threadIdx.x == 0) {
        out[Nn * OUTF]     = sb[0] / (float)NIDX;
        out[Nn * OUTF + 1] = sf[0] / (float)NIDX;
    }
}

// ---------------- launch -----------------------------------------------------
extern "C" void kernel_launch(void* const* d_in, const int* in_sizes, int n_in,
                              void* d_out, int out_size) {
    const float* x      = (const float*)d_in[0];
    const float* W      = (const float*)d_in[1];
    const float* b      = (const float*)d_in[2];
    const float* a      = (const float*)d_in[3];
    const float* Wg     = (const float*)d_in[4];
    const float* Wb     = (const float*)d_in[5];
    const float* bg     = (const float*)d_in[6];
    const float* bb     = (const float*)d_in[7];
    const float* Wadd   = (const float*)d_in[8];
    const float* Wrev   = (const float*)d_in[9];
    const float* PE     = (const float*)d_in[10];
    const int*   edge   = (const int*)d_in[11];
    const int*   degree = (const int*)d_in[12];
    const int*   idx    = (const int*)d_in[13];
    float* out = (float*)d_out;

    cudaFuncSetAttribute(k_sh, cudaFuncAttributeMaxDynamicSharedMemorySize, SH_SMEM);
    cudaFuncSetAttribute(k_gf, cudaFuncAttributeMaxDynamicSharedMemorySize, GF_SMEM);

    k_ph<<<SBLK + NBLK + 64 + 64, 256>>>(edge, degree, W, Wadd, Wrev, Wg, Wb, bg, bb, PE);
    k_scan1<<<NBLK + 1, 256>>>();
    k_scan3b<<<NBLK, 256>>>();
    k_sh<<<SBLK + HBLK2, 256, SH_SMEM>>>(edge, x, b, a);
    k_gf<<<GBLK, 256, GF_SMEM>>>(degree, out);
    if (out_size >= Nn * OUTF + 2)
        k_loss<<<1, 256>>>(degree, idx, out);
}

// round 14
// speedup vs baseline: 1.2118x; 1.0481x over previous
#include <cuda_runtime.h>
#include <math.h>

#define Nn   50000
#define Ee   1600000
#define INF  128
#define OUTF 64
#define NIDX 5000
#define NBLK 196        // ceil(Nn/256)
#define HBLK2 782       // ceil(Nn/64)
#define GBLK 1563       // ceil(Nn/32)
#define SBLK 1563       // ceil(Ee/4/256)
#define SHBLK 2345      // SBLK + HBLK2

// ---------------- scratch (device globals) ----------------------------------
__device__ float4 g_h4[Nn * 16];
__device__ float  g_s[Nn];
__device__ float  g_t[Nn];
__device__ float  g_nadd[Nn];
__device__ float  g_nrev[Nn];
__device__ float4 g_gamtab4[256 * 16];
__device__ float4 g_bettab4[256 * 16];
__device__ float  g_ngamtab[256];
__device__ float  g_nbettab[256];
__device__ float  g_Wt[INF * OUTF];
__device__ float  g_WaT[OUTF * OUTF];
__device__ float  g_WrT[OUTF * OUTF];
__device__ int    g_cnt[Nn];          // zero at module load; re-zeroed by k_scan3b
__device__ int    g_off[Nn + 1];
__device__ int    g_cur[Nn];
__device__ int    g_dsts[Ee];
__device__ int    g_bsum[NBLK];
__device__ int    g_dpart[NBLK];
__device__ float  g_Kthr;

__device__ __forceinline__ float lrelu(float v) { return v > 0.f ? v : 0.01f * v; }

// ---------------- PH: hist + degree partials + transposes + gbtab -----------
__global__ void k_ph(const int* __restrict__ edge, const int* __restrict__ degree,
                     const float* __restrict__ W, const float* __restrict__ Wa,
                     const float* __restrict__ Wr, const float* __restrict__ Wg_,
                     const float* __restrict__ Wb_, const float* __restrict__ bg,
                     const float* __restrict__ bb, const float* __restrict__ PE) {
    int blk = blockIdx.x, tid = threadIdx.x;
    if (blk < SBLK) {                             // ---- edge histogram (int4) ----
        int t = blk * 256 + tid;
        if (t < Ee / 4) {
            int4 e = ((const int4*)edge)[t];
            atomicAdd(&g_cnt[e.x], 1);
            atomicAdd(&g_cnt[e.y], 1);
            atomicAdd(&g_cnt[e.z], 1);
            atomicAdd(&g_cnt[e.w], 1);
        }
        return;
    }
    if (blk < SBLK + NBLK) {                      // ---- degree partial sums ----
        __shared__ int ws[8];
        int bb2 = blk - SBLK;
        int t = bb2 * 256 + tid;
        int d = (t < Nn) ? degree[t] : 0;
        #pragma unroll
        for (int o = 16; o; o >>= 1) d += __shfl_down_sync(0xFFFFFFFFu, d, o);
        int lane = tid & 31, w = tid >> 5;
        if (lane == 0) ws[w] = d;
        __syncthreads();
        if (tid == 0) {
            int s = 0;
            #pragma unroll
            for (int q = 0; q < 8; q++) s += ws[q];
            g_dpart[bb2] = s;
        }
        return;
    }
    if (blk < SBLK + NBLK + 64) {                 // ---- weight transposes ----
        int t = (blk - SBLK - NBLK) * 256 + tid;
        if (t < 8192) {
            int k = t >> 6, j = t & 63;
            g_Wt[t] = W[j * 128 + k];
        } else if (t < 12288) {
            int p = t - 8192; int k = p >> 6, j = p & 63;
            g_WaT[p] = Wa[j * 64 + k];
        } else {
            int p = t - 12288; int k = p >> 6, j = p & 63;
            g_WrT[p] = Wr[j * 64 + k];
        }
        return;
    }
    // ---- gamma/beta tables over 256 degrees ----
    __shared__ float Wg[4096], Wb[4096];
    __shared__ float ms[4][64];
    __shared__ float pG[8], pB[8];
    for (int p = tid; p < 4096; p += 256) { Wg[p] = Wg_[p]; Wb[p] = Wb_[p]; }
    int local = tid >> 6, j = tid & 63;
    int d = (blk - SBLK - NBLK - 64) * 4 + local;
    ms[local][j] = PE[d * 64 + j];
    __syncthreads();
    float ag = bg[j], ab = bb[j];
    #pragma unroll
    for (int k = 0; k < 64; k++) {
        float m = ms[local][k];
        ag += m * Wg[k * 64 + j];
        ab += m * Wb[k * 64 + j];
    }
    float gam = lrelu(ag), bet = lrelu(ab);
    ((float*)g_gamtab4)[d * 64 + j] = gam;
    ((float*)g_bettab4)[d * 64 + j] = bet;
    float pg = gam * gam, pb = bet * bet;
    #pragma unroll
    for (int o = 16; o; o >>= 1) {
        pg += __shfl_down_sync(0xFFFFFFFFu, pg, o);
        pb += __shfl_down_sync(0xFFFFFFFFu, pb, o);
    }
    int w = tid >> 5;
    if ((tid & 31) == 0) { pG[w] = pg; pB[w] = pb; }
    __syncthreads();
    if (j == 0) {
        g_ngamtab[d] = sqrtf(pG[2 * local] + pG[2 * local + 1]);
        g_nbettab[d] = sqrtf(pB[2 * local] + pB[2 * local + 1]);
    }
}

// ---------------- S1: per-block sums + degsum reduction ----------------------
__global__ void k_scan1() {
    __shared__ int ws[8];
    int tid = threadIdx.x;
    int lane = tid & 31, w = tid >> 5;
    if (blockIdx.x == NBLK) {
        int v = (tid < NBLK) ? g_dpart[tid] : 0;
        #pragma unroll
        for (int o = 16; o; o >>= 1) v += __shfl_down_sync(0xFFFFFFFFu, v, o);
        if (lane == 0) ws[w] = v;
        __syncthreads();
        if (tid == 0) {
            int s = 0;
            #pragma unroll
            for (int q = 0; q < 8; q++) s += ws[q];
            g_Kthr = (float)((double)s / (double)Nn);
        }
        return;
    }
    int i = blockIdx.x * 256 + tid;
    int v = (i < Nn) ? g_cnt[i] : 0;
    int s = v;
    #pragma unroll
    for (int o = 16; o; o >>= 1) s += __shfl_down_sync(0xFFFFFFFFu, s, o);
    if (lane == 0) ws[w] = s;
    __syncthreads();
    if (tid == 0) {
        int t = 0;
        #pragma unroll
        for (int q = 0; q < 8; q++) t += ws[q];
        g_bsum[blockIdx.x] = t;
    }
}

// ---------------- S3: replicated block-sum scan + local scan + cnt re-zero ---
__global__ void k_scan3b() {
    __shared__ int ws[8];
    __shared__ int base_s, tot_s;
    int tid = threadIdx.x;
    int lane = tid & 31, w = tid >> 5;
    {
        int v = (tid < NBLK) ? g_bsum[tid] : 0;
        int orig = v;
        #pragma unroll
        for (int o = 1; o < 32; o <<= 1) { int u = __shfl_up_sync(0xFFFFFFFFu, v, o); if (lane >= o) v += u; }
        if (lane == 31) ws[w] = v;
        __syncthreads();
        if (w == 0 && lane < 8) {
            int u = ws[lane];
            #pragma unroll
            for (int o = 1; o < 8; o <<= 1) { int z = __shfl_up_sync(0xFFu, u, o); if (lane >= o) u += z; }
            ws[lane] = u;
        }
        __syncthreads();
        int incl = v + (w ? ws[w - 1] : 0);
        if (tid == (int)blockIdx.x) base_s = incl - orig;
        if (tid == NBLK - 1) tot_s = incl;
        __syncthreads();
    }
    int i = blockIdx.x * 256 + tid;
    int c = (i < Nn) ? g_cnt[i] : 0;
    int corig = c;
    #pragma unroll
    for (int o = 1; o < 32; o <<= 1) { int u = __shfl_up_sync(0xFFFFFFFFu, c, o); if (lane >= o) c += u; }
    if (lane == 31) ws[w] = c;
    __syncthreads();
    if (w == 0 && lane < 8) {
        int u = ws[lane];
        #pragma unroll
        for (int o = 1; o < 8; o <<= 1) { int z = __shfl_up_sync(0xFFu, u, o); if (lane >= o) u += z; }
        ws[lane] = u;
    }
    __syncthreads();
    int excl = c - corig + (w ? ws[w - 1] : 0) + base_s;
    if (i < Nn) {
        g_off[i] = excl; g_cur[i] = excl;
        g_cnt[i] = 0;
    }
    if (blockIdx.x == 0 && tid == 0) g_off[Nn] = tot_s;
}

// ---------------- SH: scatter + h-GEMM, roles INTERLEAVED across blocks ------
// blk % 3 == 1 -> GEMM block (782 total); else scatter block (1563 total).
// Every scheduling wave mixes L2-atomic-bound and FMA-bound blocks.
#define SH_SMEM 49152
__global__ void __launch_bounds__(256) k_sh(const int* __restrict__ edge,
                                            const float* __restrict__ x,
                                            const float* __restrict__ b,
                                            const float* __restrict__ a) {
    extern __shared__ float4 sh4[];
    float4* Ws = sh4;            // 128*16 float4 = 32KB
    float4* xs = sh4 + 2048;     // 64 nodes * 16 kq float4 = 16KB (reused 2x)
    int blk = blockIdx.x;
    int rem = blk % 3;
    if (rem != 1) {                   // -------- scatter branch --------
        int sidx = 2 * (blk / 3) + ((rem == 2) ? 1 : 0);
        int t = sidx * 256 + threadIdx.x;
        if (t < Ee / 4) {
            int4 s4 = ((const int4*)edge)[t];
            int4 d4 = ((const int4*)(edge + Ee))[t];
            int p;
            p = atomicAdd(&g_cur[s4.x], 1); g_dsts[p] = d4.x;
            p = atomicAdd(&g_cur[s4.y], 1); g_dsts[p] = d4.y;
            p = atomicAdd(&g_cur[s4.z], 1); g_dsts[p] = d4.z;
            p = atomicAdd(&g_cur[s4.w], 1); g_dsts[p] = d4.w;
        }
        return;
    }
    // -------- h = (xW^T+b)*8 ; s,t projections : 64 nodes, 4 per thread ------
    int gidx = blk / 3;               // 0..781
    int tid = threadIdx.x;
    const float4* Wt4 = (const float4*)g_Wt;
    for (int p = tid; p < 2048; p += 256) Ws[p] = Wt4[p];
    int n0 = gidx * 64;
    const float4* x4 = (const float4*)x;

    int og = tid & 15, ng = tid >> 4;       // 16 output-groups x 16 node-groups
    int nbase = 4 * ng;
    float4 acc0 = make_float4(0.f, 0.f, 0.f, 0.f);
    float4 acc1 = acc0, acc2 = acc0, acc3 = acc0;

    #pragma unroll
    for (int hf = 0; hf < 2; hf++) {
        __syncthreads();   // first iter: covers Ws staging; later: xs reuse
        for (int p = tid; p < 1024; p += 256) {
            int n = p >> 4, kq = p & 15;
            int node = n0 + n;
            xs[p] = (node < Nn) ? x4[node * 32 + hf * 16 + kq]
                                : make_float4(0.f, 0.f, 0.f, 0.f);
        }
        __syncthreads();
        #pragma unroll 4
        for (int kq = 0; kq < 16; kq++) {
            int kg = hf * 16 + kq;
            float4 w0 = Ws[(4 * kg + 0) * 16 + og];
            float4 w1 = Ws[(4 * kg + 1) * 16 + og];
            float4 w2 = Ws[(4 * kg + 2) * 16 + og];
            float4 w3 = Ws[(4 * kg + 3) * 16 + og];
            float4 x0 = xs[(nbase + 0) * 16 + kq];
            float4 x1 = xs[(nbase + 1) * 16 + kq];
            float4 x2 = xs[(nbase + 2) * 16 + kq];
            float4 x3 = xs[(nbase + 3) * 16 + kq];
            acc0.x += x0.x * w0.x + x0.y * w1.x + x0.z * w2.x + x0.w * w3.x;
            acc0.y += x0.x * w0.y + x0.y * w1.y + x0.z * w2.y + x0.w * w3.y;
            acc0.z += x0.x * w0.z + x0.y * w1.z + x0.z * w2.z + x0.w * w3.z;
            acc0.w += x0.x * w0.w + x0.y * w1.w + x0.z * w2.w + x0.w * w3.w;
            acc1.x += x1.x * w0.x + x1.y * w1.x + x1.z * w2.x + x1.w * w3.x;
            acc1.y += x1.x * w0.y + x1.y * w1.y + x1.z * w2.y + x1.w * w3.y;
            acc1.z += x1.x * w0.z + x1.y * w1.z + x1.z * w2.z + x1.w * w3.z;
            acc1.w += x1.x * w0.w + x1.y * w1.w + x1.z * w2.w + x1.w * w3.w;
            acc2.x += x2.x * w0.x + x2.y * w1.x + x2.z * w2.x + x2.w * w3.x;
            acc2.y += x2.x * w0.y + x2.y * w1.y + x2.z * w2.y + x2.w * w3.y;
            acc2.z += x2.x * w0.z + x2.y * w1.z + x2.z * w2.z + x2.w * w3.z;
            acc2.w += x2.x * w0.w + x2.y * w1.w + x2.z * w2.w + x2.w * w3.w;
            acc3.x += x3.x * w0.x + x3.y * w1.x + x3.z * w2.x + x3.w * w3.x;
            acc3.y += x3.x * w0.y + x3.y * w1.y + x3.z * w2.y + x3.w * w3.y;
            acc3.z += x3.x * w0.z + x3.y * w1.z + x3.z * w2.z + x3.w * w3.z;
            acc3.w += x3.x * w0.w + x3.y * w1.w + x3.z * w2.w + x3.w * w3.w;
        }
    }
    float4 b4  = ((const float4*)b)[og];
    float4 as4 = ((const float4*)a)[og];
    float4 at4 = ((const float4*)a)[16 + og];
    #pragma unroll
    for (int i = 0; i < 4; i++) {
        float4 A = (i == 0) ? acc0 : (i == 1) ? acc1 : (i == 2) ? acc2 : acc3;
        float4 h = make_float4((A.x + b4.x) * 8.f, (A.y + b4.y) * 8.f,
                               (A.z + b4.z) * 8.f, (A.w + b4.w) * 8.f);
        int node = n0 + nbase + i;
        if (node < Nn) g_h4[node * 16 + og] = h;
        float sv = h.x * as4.x + h.y * as4.y + h.z * as4.z + h.w * as4.w;
        float tv = h.x * at4.x + h.y * at4.y + h.z * at4.z + h.w * at4.w;
        #pragma unroll
        for (int o = 8; o; o >>= 1) {
            sv += __shfl_down_sync(0xFFFFFFFFu, sv, o, 16);
            tv += __shfl_down_sync(0xFFFFFFFFu, tv, o, 16);
        }
        if (og == 0 && node < Nn) { g_s[node] = sv; g_t[node] = tv; }
    }
}

// ---------------- GF: fused gather (half-warp/edge, float4) + epilogue -------
#define GF_SMEM 49536
__global__ void __launch_bounds__(256) k_gf(const int* __restrict__ degree,
                                            float* __restrict__ out) {
    extern __shared__ float sm[];
    float4* WsA  = (float4*)sm;
    float4* WsR  = WsA + 1024;
    float*  sAgg = sm + 8192;
    float*  sHp  = sAgg + 2048;
    float*  sRs  = sHp + 2048;
    float*  sInv = sRs + 32;
    int*    sDeg = (int*)(sInv + 32);
    int tid = threadIdx.x;
    const float4* Wa4 = (const float4*)g_WaT;
    const float4* Wr4 = (const float4*)g_WrT;
    for (int p = tid; p < 1024; p += 256) { WsA[p] = Wa4[p]; WsR[p] = Wr4[p]; }
    int n0 = blockIdx.x * 32;
    if (tid < 32) {
        int node = n0 + tid;
        int d = (node < Nn) ? degree[node] : 1;
        sDeg[tid] = d;
        sInv[tid] = (d == 0) ? 0.f : 1.f / (float)d;
    }
    int w = tid >> 5, lane = tid & 31;
    int lq = lane & 15, half = lane >> 4;
    const float4* h4 = (const float4*)g_h4;
    #pragma unroll
    for (int k = 0; k < 4; k++) {
        int nl = w + 8 * k;
        int node = n0 + nl;
        float4 acc  = make_float4(0.f, 0.f, 0.f, 0.f);
        float4 wacc = acc;
        float rs = 0.f;
        if (node < Nn) {
            int s0 = g_off[node], s1 = g_off[node + 1];
            float ssrc = g_s[node];
            for (int base = s0; base < s1; base += 32) {
                int m = s1 - base; if (m > 32) m = 32;
                int dst = 0; float ev = 0.f;
                if (lane < m) {
                    dst = g_dsts[base + lane];
                    float z = ssrc + g_t[dst];
                    ev = __expf(-(z > 0.f ? z : 0.01f * z));
                    rs += ev;
                }
                if (m == 32) {
                    #pragma unroll 8
                    for (int p = 0; p < 16; p++) {
                        int j = 2 * p + half;
                        int  dd = __shfl_sync(0xFFFFFFFFu, dst, j);
                        float e = __shfl_sync(0xFFFFFFFFu, ev, j);
                        float4 v = h4[dd * 16 + lq];
                        acc.x += v.x;  acc.y += v.y;  acc.z += v.z;  acc.w += v.w;
                        wacc.x += e * v.x; wacc.y += e * v.y;
                        wacc.z += e * v.z; wacc.w += e * v.w;
                    }
                } else {
                    int pm = (m + 1) >> 1;
                    for (int p = 0; p < pm; p++) {
                        int j = 2 * p + half;
                        int jj = (j < m) ? j : 0;
                        int  dd = __shfl_sync(0xFFFFFFFFu, dst, jj);
                        float e = __shfl_sync(0xFFFFFFFFu, ev, jj);
                        if (j < m) {
                            float4 v = h4[dd * 16 + lq];
                            acc.x += v.x;  acc.y += v.y;  acc.z += v.z;  acc.w += v.w;
                            wacc.x += e * v.x; wacc.y += e * v.y;
                            wacc.z += e * v.z; wacc.w += e * v.w;
                        }
                    }
                }
            }
        }
        acc.x  += __shfl_down_sync(0xFFFFFFFFu, acc.x, 16);
        acc.y  += __shfl_down_sync(0xFFFFFFFFu, acc.y, 16);
        acc.z  += __shfl_down_sync(0xFFFFFFFFu, acc.z, 16);
        acc.w  += __shfl_down_sync(0xFFFFFFFFu, acc.w, 16);
        wacc.x += __shfl_down_sync(0xFFFFFFFFu, wacc.x, 16);
        wacc.y += __shfl_down_sync(0xFFFFFFFFu, wacc.y, 16);
        wacc.z += __shfl_down_sync(0xFFFFFFFFu, wacc.z, 16);
        wacc.w += __shfl_down_sync(0xFFFFFFFFu, wacc.w, 16);
        if (lane < 16) {
            ((float4*)sAgg)[nl * 16 + lq] = acc;
            ((float4*)sHp)[nl * 16 + lq]  = wacc;
        }
        #pragma unroll
        for (int o = 16; o; o >>= 1) rs += __shfl_down_sync(0xFFFFFFFFu, rs, o);
        if (lane == 0) sRs[nl] = rs;
    }
    __syncthreads();
    for (int p = tid; p < 2048; p += 256) sAgg[p] *= sInv[p >> 6];
    __syncthreads();

    int og = tid & 15, ng = tid >> 4;
    int na = 2 * ng, nb = na + 1;
    const float4* is4 = (const float4*)sAgg;
    float4 Aa = make_float4(0.f, 0.f, 0.f, 0.f), Ra = Aa, Ab = Aa, Rb = Aa;
    #pragma unroll 4
    for (int kq = 0; kq < 16; kq++) {
        float4 xa = is4[na * 16 + kq];
        float4 xb = is4[nb * 16 + kq];
        #pragma unroll
        for (int r = 0; r < 4; r++) {
            float4 wa = WsA[(4 * kq + r) * 16 + og];
            float4 wr = WsR[(4 * kq + r) * 16 + og];
            float xav = (r == 0) ? xa.x : (r == 1) ? xa.y : (r == 2) ? xa.z : xa.w;
            float xbv = (r == 0) ? xb.x : (r == 1) ? xb.y : (r == 2) ? xb.z : xb.w;
            Aa.x += xav * wa.x; Aa.y += xav * wa.y; Aa.z += xav * wa.z; Aa.w += xav * wa.w;
            Ra.x += xav * wr.x; Ra.y += xav * wr.y; Ra.z += xav * wr.z; Ra.w += xav * wr.w;
            Ab.x += xbv * wa.x; Ab.y += xbv * wa.y; Ab.z += xbv * wa.z; Ab.w += xbv * wa.w;
            Rb.x += xbv * wr.x; Rb.y += xbv * wr.y; Rb.z += xbv * wr.z; Rb.w += xbv * wr.w;
        }
    }
    float Kthr = g_Kthr;

    #pragma unroll
    for (int hh = 0; hh < 2; hh++) {
        int nl = hh ? nb : na;
        int node = n0 + nl;
        float4 Av = hh ? Ab : Aa;
        float4 Rv = hh ? Rb : Ra;
        float pa = 0.f, pr = 0.f;
        float4 o4 = make_float4(0.f, 0.f, 0.f, 0.f);
        if (node < Nn) {
            int d = sDeg[nl];
            float4 gam = g_gamtab4[d * 16 + og];
            float4 bet = g_bettab4[d * 16 + og];
            float4 ba, br;
            ba.x = (gam.x + 1.f) * Av.x + bet.x;  br.x = (gam.x + 1.f) * Rv.x + bet.x;
            ba.y = (gam.y + 1.f) * Av.y + bet.y;  br.y = (gam.y + 1.f) * Rv.y + bet.y;
            ba.z = (gam.z + 1.f) * Av.z + bet.z;  br.z = (gam.z + 1.f) * Rv.z + bet.z;
            ba.w = (gam.w + 1.f) * Av.w + bet.w;  br.w = (gam.w + 1.f) * Rv.w + bet.w;
            float R = ((float)d < Kthr) ? 1.f : 0.f;
            const float4* hp4 = (const float4*)sHp;
            float4 hp = hp4[nl * 16 + og];
            float inv = 1.f / (sRs[nl] + 1e-5f + 1.f);
            float bx = 0.1f * (R * ba.x - (1.f - R) * br.x);
            float by = 0.1f * (R * ba.y - (1.f - R) * br.y);
            float bz = 0.1f * (R * ba.z - (1.f - R) * br.z);
            float bw = 0.1f * (R * ba.w - (1.f - R) * br.w);
            o4.x = lrelu((hp.x + bx) * inv);
            o4.y = lrelu((hp.y + by) * inv);
            o4.z = lrelu((hp.z + bz) * inv);
            o4.w = lrelu((hp.w + bw) * inv);
            pa = ba.x * ba.x + ba.y * ba.y + ba.z * ba.z + ba.w * ba.w;
            pr = br.x * br.x + br.y * br.y + br.z * br.z + br.w * br.w;
        }
        #pragma unroll
        for (int o = 8; o; o >>= 1) {
            pa += __shfl_down_sync(0xFFFFFFFFu, pa, o, 16);
            pr += __shfl_down_sync(0xFFFFFFFFu, pr, o, 16);
        }
        if (node < Nn) {
            ((float4*)out)[node * 16 + og] = o4;
            if (og == 0) { g_nadd[node] = sqrtf(pa); g_nrev[node] = sqrtf(pr); }
        }
    }
}

// ---------------- L: loss reductions over idx -------------------------------
__global__ void k_loss(const int* __restrict__ degree, const int* __restrict__ idx,
                       float* __restrict__ out) {
    __shared__ float sb[256], sf[256];
    float Kthr = g_Kthr;
    float lb = 0.f, lf = 0.f;
    for (int i = threadIdx.x; i < NIDX; i += 256) {
        int r = idx[i];
        int d = degree[r];
        bool R = ((float)d) < Kthr;
        lb += R ? g_nadd[r] : g_nrev[r];
        lf += g_ngamtab[d] + g_nbettab[d];
    }
    sb[threadIdx.x] = lb; sf[threadIdx.x] = lf;
    __syncthreads();
    for (int s = 128; s; s >>= 1) {
        if (threadIdx.x < (unsigned)s) {
            sb[threadIdx.x] += sb[threadIdx.x + s];
            sf[threadIdx.x] += sf[threadIdx.x + s];
        }
        __syncthreads();
    }
    if (threadIdx.x == 0) {
        out[Nn * OUTF]     = sb[0] / (float)NIDX;
        out[Nn * OUTF + 1] = sf[0] / (float)NIDX;
    }
}

// ---------------- launch -----------------------------------------------------
extern "C" void kernel_launch(void* const* d_in, const int* in_sizes, int n_in,
                              void* d_out, int out_size) {
    const float* x      = (const float*)d_in[0];
    const float* W      = (const float*)d_in[1];
    const float* b      = (const float*)d_in[2];
    const float* a      = (const float*)d_in[3];
    const float* Wg     = (const float*)d_in[4];
    const float* Wb     = (const float*)d_in[5];
    const float* bg     = (const float*)d_in[6];
    const float* bb     = (const float*)d_in[7];
    const float* Wadd   = (const float*)d_in[8];
    const float* Wrev   = (const float*)d_in[9];
    const float* PE     = (const float*)d_in[10];
    const int*   edge   = (const int*)d_in[11];
    const int*   degree = (const int*)d_in[12];
    const int*   idx    = (const int*)d_in[13];
    float* out = (float*)d_out;

    cudaFuncSetAttribute(k_sh, cudaFuncAttributeMaxDynamicSharedMemorySize, SH_SMEM);
    cudaFuncSetAttribute(k_gf, cudaFuncAttributeMaxDynamicSharedMemorySize, GF_SMEM);

    k_ph<<<SBLK + NBLK + 64 + 64, 256>>>(edge, degree, W, Wadd, Wrev, Wg, Wb, bg, bb, PE);
    k_scan1<<<NBLK + 1, 256>>>();
    k_scan3b<<<NBLK, 256>>>();
    k_sh<<<SHBLK, 256, SH_SMEM>>>(edge, x, b, a);
    k_gf<<<GBLK, 256, GF_SMEM>>>(degree, out);
    if (out_size >= Nn * OUTF + 2)
        k_loss<<<1, 256>>>(degree, idx, out);
}

// round 15
// speedup vs baseline: 1.2256x; 1.0115x over previous
#include <cuda_runtime.h>
#include <cuda_fp16.h>
#include <math.h>

#define Nn   50000
#define Ee   1600000
#define INF  128
#define OUTF 64
#define NIDX 5000
#define NBLK 196        // ceil(Nn/256)
#define HBLK2 782       // ceil(Nn/64)
#define GBLK 1563       // ceil(Nn/32)
#define SBLK 1563       // ceil(Ee/4/256)
#define SHBLK 2345      // SBLK + HBLK2

// ---------------- scratch (device globals) ----------------------------------
__device__ uint2  g_hh[Nn * 16];      // h as fp16: 16 x uint2 = 64 halves per node
__device__ float  g_s[Nn];
__device__ float  g_t[Nn];
__device__ float  g_nadd[Nn];
__device__ float  g_nrev[Nn];
__device__ float4 g_gamtab4[256 * 16];
__device__ float4 g_bettab4[256 * 16];
__device__ float  g_ngamtab[256];
__device__ float  g_nbettab[256];
__device__ float  g_Wt[INF * OUTF];
__device__ float  g_WaT[OUTF * OUTF];
__device__ float  g_WrT[OUTF * OUTF];
__device__ int    g_cnt[Nn];          // zero at module load; re-zeroed by k_scan3b
__device__ int    g_off[Nn + 1];
__device__ int    g_cur[Nn];
__device__ int    g_dsts[Ee];
__device__ int    g_bsum[NBLK];
__device__ int    g_dpart[NBLK];
__device__ float  g_Kthr;

__device__ __forceinline__ float lrelu(float v) { return v > 0.f ? v : 0.01f * v; }

// ---------------- PH: hist + degree partials + transposes + gbtab -----------
__global__ void k_ph(const int* __restrict__ edge, const int* __restrict__ degree,
                     const float* __restrict__ W, const float* __restrict__ Wa,
                     const float* __restrict__ Wr, const float* __restrict__ Wg_,
                     const float* __restrict__ Wb_, const float* __restrict__ bg,
                     const float* __restrict__ bb, const float* __restrict__ PE) {
    int blk = blockIdx.x, tid = threadIdx.x;
    if (blk < SBLK) {                             // ---- edge histogram (int4) ----
        int t = blk * 256 + tid;
        if (t < Ee / 4) {
            int4 e = ((const int4*)edge)[t];
            atomicAdd(&g_cnt[e.x], 1);
            atomicAdd(&g_cnt[e.y], 1);
            atomicAdd(&g_cnt[e.z], 1);
            atomicAdd(&g_cnt[e.w], 1);
        }
        return;
    }
    if (blk < SBLK + NBLK) {                      // ---- degree partial sums ----
        __shared__ int ws[8];
        int bb2 = blk - SBLK;
        int t = bb2 * 256 + tid;
        int d = (t < Nn) ? degree[t] : 0;
        #pragma unroll
        for (int o = 16; o; o >>= 1) d += __shfl_down_sync(0xFFFFFFFFu, d, o);
        int lane = tid & 31, w = tid >> 5;
        if (lane == 0) ws[w] = d;
        __syncthreads();
        if (tid == 0) {
            int s = 0;
            #pragma unroll
            for (int q = 0; q < 8; q++) s += ws[q];
            g_dpart[bb2] = s;
        }
        return;
    }
    if (blk < SBLK + NBLK + 64) {                 // ---- weight transposes ----
        int t = (blk - SBLK - NBLK) * 256 + tid;
        if (t < 8192) {
            int k = t >> 6, j = t & 63;
            g_Wt[t] = W[j * 128 + k];
        } else if (t < 12288) {
            int p = t - 8192; int k = p >> 6, j = p & 63;
            g_WaT[p] = Wa[j * 64 + k];
        } else {
            int p = t - 12288; int k = p >> 6, j = p & 63;
            g_WrT[p] = Wr[j * 64 + k];
        }
        return;
    }
    // ---- gamma/beta tables over 256 degrees ----
    __shared__ float Wg[4096], Wb[4096];
    __shared__ float ms[4][64];
    __shared__ float pG[8], pB[8];
    for (int p = tid; p < 4096; p += 256) { Wg[p] = Wg_[p]; Wb[p] = Wb_[p]; }
    int local = tid >> 6, j = tid & 63;
    int d = (blk - SBLK - NBLK - 64) * 4 + local;
    ms[local][j] = PE[d * 64 + j];
    __syncthreads();
    float ag = bg[j], ab = bb[j];
    #pragma unroll
    for (int k = 0; k < 64; k++) {
        float m = ms[local][k];
        ag += m * Wg[k * 64 + j];
        ab += m * Wb[k * 64 + j];
    }
    float gam = lrelu(ag), bet = lrelu(ab);
    ((float*)g_gamtab4)[d * 64 + j] = gam;
    ((float*)g_bettab4)[d * 64 + j] = bet;
    float pg = gam * gam, pb = bet * bet;
    #pragma unroll
    for (int o = 16; o; o >>= 1) {
        pg += __shfl_down_sync(0xFFFFFFFFu, pg, o);
        pb += __shfl_down_sync(0xFFFFFFFFu, pb, o);
    }
    int w = tid >> 5;
    if ((tid & 31) == 0) { pG[w] = pg; pB[w] = pb; }
    __syncthreads();
    if (j == 0) {
        g_ngamtab[d] = sqrtf(pG[2 * local] + pG[2 * local + 1]);
        g_nbettab[d] = sqrtf(pB[2 * local] + pB[2 * local + 1]);
    }
}

// ---------------- S1: per-block sums + degsum reduction ----------------------
__global__ void k_scan1() {
    __shared__ int ws[8];
    int tid = threadIdx.x;
    int lane = tid & 31, w = tid >> 5;
    if (blockIdx.x == NBLK) {
        int v = (tid < NBLK) ? g_dpart[tid] : 0;
        #pragma unroll
        for (int o = 16; o; o >>= 1) v += __shfl_down_sync(0xFFFFFFFFu, v, o);
        if (lane == 0) ws[w] = v;
        __syncthreads();
        if (tid == 0) {
            int s = 0;
            #pragma unroll
            for (int q = 0; q < 8; q++) s += ws[q];
            g_Kthr = (float)((double)s / (double)Nn);
        }
        return;
    }
    int i = blockIdx.x * 256 + tid;
    int v = (i < Nn) ? g_cnt[i] : 0;
    int s = v;
    #pragma unroll
    for (int o = 16; o; o >>= 1) s += __shfl_down_sync(0xFFFFFFFFu, s, o);
    if (lane == 0) ws[w] = s;
    __syncthreads();
    if (tid == 0) {
        int t = 0;
        #pragma unroll
        for (int q = 0; q < 8; q++) t += ws[q];
        g_bsum[blockIdx.x] = t;
    }
}

// ---------------- S3: replicated block-sum scan + local scan + cnt re-zero ---
__global__ void k_scan3b() {
    __shared__ int ws[8];
    __shared__ int base_s, tot_s;
    int tid = threadIdx.x;
    int lane = tid & 31, w = tid >> 5;
    {
        int v = (tid < NBLK) ? g_bsum[tid] : 0;
        int orig = v;
        #pragma unroll
        for (int o = 1; o < 32; o <<= 1) { int u = __shfl_up_sync(0xFFFFFFFFu, v, o); if (lane >= o) v += u; }
        if (lane == 31) ws[w] = v;
        __syncthreads();
        if (w == 0 && lane < 8) {
            int u = ws[lane];
            #pragma unroll
            for (int o = 1; o < 8; o <<= 1) { int z = __shfl_up_sync(0xFFu, u, o); if (lane >= o) u += z; }
            ws[lane] = u;
        }
        __syncthreads();
        int incl = v + (w ? ws[w - 1] : 0);
        if (tid == (int)blockIdx.x) base_s = incl - orig;
        if (tid == NBLK - 1) tot_s = incl;
        __syncthreads();
    }
    int i = blockIdx.x * 256 + tid;
    int c = (i < Nn) ? g_cnt[i] : 0;
    int corig = c;
    #pragma unroll
    for (int o = 1; o < 32; o <<= 1) { int u = __shfl_up_sync(0xFFFFFFFFu, c, o); if (lane >= o) c += u; }
    if (lane == 31) ws[w] = c;
    __syncthreads();
    if (w == 0 && lane < 8) {
        int u = ws[lane];
        #pragma unroll
        for (int o = 1; o < 8; o <<= 1) { int z = __shfl_up_sync(0xFFu, u, o); if (lane >= o) u += z; }
        ws[lane] = u;
    }
    __syncthreads();
    int excl = c - corig + (w ? ws[w - 1] : 0) + base_s;
    if (i < Nn) {
        g_off[i] = excl; g_cur[i] = excl;
        g_cnt[i] = 0;
    }
    if (blockIdx.x == 0 && tid == 0) g_off[Nn] = tot_s;
}

// ---------------- SH: scatter + h-GEMM, roles INTERLEAVED across blocks ------
#define SH_SMEM 49152
__global__ void __launch_bounds__(256) k_sh(const int* __restrict__ edge,
                                            const float* __restrict__ x,
                                            const float* __restrict__ b,
                                            const float* __restrict__ a) {
    extern __shared__ float4 sh4[];
    float4* Ws = sh4;            // 128*16 float4 = 32KB
    float4* xs = sh4 + 2048;     // 64 nodes * 16 kq float4 = 16KB (reused 2x)
    int blk = blockIdx.x;
    int rem = blk % 3;
    if (rem != 1) {                   // -------- scatter branch --------
        int sidx = 2 * (blk / 3) + ((rem == 2) ? 1 : 0);
        int t = sidx * 256 + threadIdx.x;
        if (t < Ee / 4) {
            int4 s4 = ((const int4*)edge)[t];
            int4 d4 = ((const int4*)(edge + Ee))[t];
            int p;
            p = atomicAdd(&g_cur[s4.x], 1); g_dsts[p] = d4.x;
            p = atomicAdd(&g_cur[s4.y], 1); g_dsts[p] = d4.y;
            p = atomicAdd(&g_cur[s4.z], 1); g_dsts[p] = d4.z;
            p = atomicAdd(&g_cur[s4.w], 1); g_dsts[p] = d4.w;
        }
        return;
    }
    // -------- h = (xW^T+b)*8 ; s,t projections : 64 nodes, 4 per thread ------
    int gidx = blk / 3;               // 0..781
    int tid = threadIdx.x;
    const float4* Wt4 = (const float4*)g_Wt;
    for (int p = tid; p < 2048; p += 256) Ws[p] = Wt4[p];
    int n0 = gidx * 64;
    const float4* x4 = (const float4*)x;

    int og = tid & 15, ng = tid >> 4;       // 16 output-groups x 16 node-groups
    int nbase = 4 * ng;
    float4 acc0 = make_float4(0.f, 0.f, 0.f, 0.f);
    float4 acc1 = acc0, acc2 = acc0, acc3 = acc0;

    #pragma unroll
    for (int hf = 0; hf < 2; hf++) {
        __syncthreads();   // first iter: covers Ws staging; later: xs reuse
        for (int p = tid; p < 1024; p += 256) {
            int n = p >> 4, kq = p & 15;
            int node = n0 + n;
            xs[p] = (node < Nn) ? x4[node * 32 + hf * 16 + kq]
                                : make_float4(0.f, 0.f, 0.f, 0.f);
        }
        __syncthreads();
        #pragma unroll 4
        for (int kq = 0; kq < 16; kq++) {
            int kg = hf * 16 + kq;
            float4 w0 = Ws[(4 * kg + 0) * 16 + og];
            float4 w1 = Ws[(4 * kg + 1) * 16 + og];
            float4 w2 = Ws[(4 * kg + 2) * 16 + og];
            float4 w3 = Ws[(4 * kg + 3) * 16 + og];
            float4 x0 = xs[(nbase + 0) * 16 + kq];
            float4 x1 = xs[(nbase + 1) * 16 + kq];
            float4 x2 = xs[(nbase + 2) * 16 + kq];
            float4 x3 = xs[(nbase + 3) * 16 + kq];
            acc0.x += x0.x * w0.x + x0.y * w1.x + x0.z * w2.x + x0.w * w3.x;
            acc0.y += x0.x * w0.y + x0.y * w1.y + x0.z * w2.y + x0.w * w3.y;
            acc0.z += x0.x * w0.z + x0.y * w1.z + x0.z * w2.z + x0.w * w3.z;
            acc0.w += x0.x * w0.w + x0.y * w1.w + x0.z * w2.w + x0.w * w3.w;
            acc1.x += x1.x * w0.x + x1.y * w1.x + x1.z * w2.x + x1.w * w3.x;
            acc1.y += x1.x * w0.y + x1.y * w1.y + x1.z * w2.y + x1.w * w3.y;
            acc1.z += x1.x * w0.z + x1.y * w1.z + x1.z * w2.z + x1.w * w3.z;
            acc1.w += x1.x * w0.w + x1.y * w1.w + x1.z * w2.w + x1.w * w3.w;
            acc2.x += x2.x * w0.x + x2.y * w1.x + x2.z * w2.x + x2.w * w3.x;
            acc2.y += x2.x * w0.y + x2.y * w1.y + x2.z * w2.y + x2.w * w3.y;
            acc2.z += x2.x * w0.z + x2.y * w1.z + x2.z * w2.z + x2.w * w3.z;
            acc2.w += x2.x * w0.w + x2.y * w1.w + x2.z * w2.w + x2.w * w3.w;
            acc3.x += x3.x * w0.x + x3.y * w1.x + x3.z * w2.x + x3.w * w3.x;
            acc3.y += x3.x * w0.y + x3.y * w1.y + x3.z * w2.y + x3.w * w3.y;
            acc3.z += x3.x * w0.z + x3.y * w1.z + x3.z * w2.z + x3.w * w3.z;
            acc3.w += x3.x * w0.w + x3.y * w1.w + x3.z * w2.w + x3.w * w3.w;
        }
    }
    float4 b4  = ((const float4*)b)[og];
    float4 as4 = ((const float4*)a)[og];
    float4 at4 = ((const float4*)a)[16 + og];
    #pragma unroll
    for (int i = 0; i < 4; i++) {
        float4 A = (i == 0) ? acc0 : (i == 1) ? acc1 : (i == 2) ? acc2 : acc3;
        float4 h = make_float4((A.x + b4.x) * 8.f, (A.y + b4.y) * 8.f,
                               (A.z + b4.z) * 8.f, (A.w + b4.w) * 8.f);
        int node = n0 + nbase + i;
        if (node < Nn) {
            __half2 p01 = __float22half2_rn(make_float2(h.x, h.y));
            __half2 p23 = __float22half2_rn(make_float2(h.z, h.w));
            uint2 st;
            st.x = *reinterpret_cast<unsigned int*>(&p01);
            st.y = *reinterpret_cast<unsigned int*>(&p23);
            g_hh[node * 16 + og] = st;
        }
        float sv = h.x * as4.x + h.y * as4.y + h.z * as4.z + h.w * as4.w;
        float tv = h.x * at4.x + h.y * at4.y + h.z * at4.z + h.w * at4.w;
        #pragma unroll
        for (int o = 8; o; o >>= 1) {
            sv += __shfl_down_sync(0xFFFFFFFFu, sv, o, 16);
            tv += __shfl_down_sync(0xFFFFFFFFu, tv, o, 16);
        }
        if (og == 0 && node < Nn) { g_s[node] = sv; g_t[node] = tv; }
    }
}

// ---------------- GF: fused gather (fp16 h, half-warp/edge) + epilogue -------
#define GF_SMEM 49536
__global__ void __launch_bounds__(256) k_gf(const int* __restrict__ degree,
                                            float* __restrict__ out) {
    extern __shared__ float sm[];
    float4* WsA  = (float4*)sm;
    float4* WsR  = WsA + 1024;
    float*  sAgg = sm + 8192;
    float*  sHp  = sAgg + 2048;
    float*  sRs  = sHp + 2048;
    float*  sInv = sRs + 32;
    int*    sDeg = (int*)(sInv + 32);
    int tid = threadIdx.x;
    const float4* Wa4 = (const float4*)g_WaT;
    const float4* Wr4 = (const float4*)g_WrT;
    for (int p = tid; p < 1024; p += 256) { WsA[p] = Wa4[p]; WsR[p] = Wr4[p]; }
    int n0 = blockIdx.x * 32;
    if (tid < 32) {
        int node = n0 + tid;
        int d = (node < Nn) ? degree[node] : 1;
        sDeg[tid] = d;
        sInv[tid] = (d == 0) ? 0.f : 1.f / (float)d;
    }
    int w = tid >> 5, lane = tid & 31;
    int lq = lane & 15, half = lane >> 4;
    #pragma unroll
    for (int k = 0; k < 4; k++) {
        int nl = w + 8 * k;
        int node = n0 + nl;
        float4 acc  = make_float4(0.f, 0.f, 0.f, 0.f);
        float4 wacc = acc;
        float rs = 0.f;
        if (node < Nn) {
            int s0 = g_off[node], s1 = g_off[node + 1];
            float ssrc = g_s[node];
            for (int base = s0; base < s1; base += 32) {
                int m = s1 - base; if (m > 32) m = 32;
                int dst = 0; float ev = 0.f;
                if (lane < m) {
                    dst = g_dsts[base + lane];
                    float z = ssrc + g_t[dst];
                    ev = __expf(-(z > 0.f ? z : 0.01f * z));
                    rs += ev;
                }
                if (m == 32) {
                    #pragma unroll 8
                    for (int p = 0; p < 16; p++) {
                        int j = 2 * p + half;
                        int  dd = __shfl_sync(0xFFFFFFFFu, dst, j);
                        float e = __shfl_sync(0xFFFFFFFFu, ev, j);
                        uint2 raw = g_hh[dd * 16 + lq];
                        float2 f01 = __half22float2(*reinterpret_cast<__half2*>(&raw.x));
                        float2 f23 = __half22float2(*reinterpret_cast<__half2*>(&raw.y));
                        acc.x += f01.x;  acc.y += f01.y;  acc.z += f23.x;  acc.w += f23.y;
                        wacc.x += e * f01.x; wacc.y += e * f01.y;
                        wacc.z += e * f23.x; wacc.w += e * f23.y;
                    }
                } else {
                    int pm = (m + 1) >> 1;
                    for (int p = 0; p < pm; p++) {
                        int j = 2 * p + half;
                        int jj = (j < m) ? j : 0;
                        int  dd = __shfl_sync(0xFFFFFFFFu, dst, jj);
                        float e = __shfl_sync(0xFFFFFFFFu, ev, jj);
                        if (j < m) {
                            uint2 raw = g_hh[dd * 16 + lq];
                            float2 f01 = __half22float2(*reinterpret_cast<__half2*>(&raw.x));
                            float2 f23 = __half22float2(*reinterpret_cast<__half2*>(&raw.y));
                            acc.x += f01.x;  acc.y += f01.y;  acc.z += f23.x;  acc.w += f23.y;
                            wacc.x += e * f01.x; wacc.y += e * f01.y;
                            wacc.z += e * f23.x; wacc.w += e * f23.y;
                        }
                    }
                }
            }
        }
        acc.x  += __shfl_down_sync(0xFFFFFFFFu, acc.x, 16);
        acc.y  += __shfl_down_sync(0xFFFFFFFFu, acc.y, 16);
        acc.z  += __shfl_down_sync(0xFFFFFFFFu, acc.z, 16);
        acc.w  += __shfl_down_sync(0xFFFFFFFFu, acc.w, 16);
        wacc.x += __shfl_down_sync(0xFFFFFFFFu, wacc.x, 16);
        wacc.y += __shfl_down_sync(0xFFFFFFFFu, wacc.y, 16);
        wacc.z += __shfl_down_sync(0xFFFFFFFFu, wacc.z, 16);
        wacc.w += __shfl_down_sync(0xFFFFFFFFu, wacc.w, 16);
        if (lane < 16) {
            ((float4*)sAgg)[nl * 16 + lq] = acc;
            ((float4*)sHp)[nl * 16 + lq]  = wacc;
        }
        #pragma unroll
        for (int o = 16; o; o >>= 1) rs += __shfl_down_sync(0xFFFFFFFFu, rs, o);
        if (lane == 0) sRs[nl] = rs;
    }
    __syncthreads();
    for (int p = tid; p < 2048; p += 256) sAgg[p] *= sInv[p >> 6];
    __syncthreads();

    int og = tid & 15, ng = tid >> 4;
    int na = 2 * ng, nb = na + 1;
    const float4* is4 = (const float4*)sAgg;
    float4 Aa = make_float4(0.f, 0.f, 0.f, 0.f), Ra = Aa, Ab = Aa, Rb = Aa;
    #pragma unroll 4
    for (int kq = 0; kq < 16; kq++) {
        float4 xa = is4[na * 16 + kq];
        float4 xb = is4[nb * 16 + kq];
        #pragma unroll
        for (int r = 0; r < 4; r++) {
            float4 wa = WsA[(4 * kq + r) * 16 + og];
            float4 wr = WsR[(4 * kq + r) * 16 + og];
            float xav = (r == 0) ? xa.x : (r == 1) ? xa.y : (r == 2) ? xa.z : xa.w;
            float xbv = (r == 0) ? xb.x : (r == 1) ? xb.y : (r == 2) ? xb.z : xb.w;
            Aa.x += xav * wa.x; Aa.y += xav * wa.y; Aa.z += xav * wa.z; Aa.w += xav * wa.w;
            Ra.x += xav * wr.x; Ra.y += xav * wr.y; Ra.z += xav * wr.z; Ra.w += xav * wr.w;
            Ab.x += xbv * wa.x; Ab.y += xbv * wa.y; Ab.z += xbv * wa.z; Ab.w += xbv * wa.w;
            Rb.x += xbv * wr.x; Rb.y += xbv * wr.y; Rb.z += xbv * wr.z; Rb.w += xbv * wr.w;
        }
    }
    float Kthr = g_Kthr;

    #pragma unroll
    for (int hh = 0; hh < 2; hh++) {
        int nl = hh ? nb : na;
        int node = n0 + nl;
        float4 Av = hh ? Ab : Aa;
        float4 Rv = hh ? Rb : Ra;
        float pa = 0.f, pr = 0.f;
        float4 o4 = make_float4(0.f, 0.f, 0.f, 0.f);
        if (node < Nn) {
            int d = sDeg[nl];
            float4 gam = g_gamtab4[d * 16 + og];
            float4 bet = g_bettab4[d * 16 + og];
            float4 ba, br;
            ba.x = (gam.x + 1.f) * Av.x + bet.x;  br.x = (gam.x + 1.f) * Rv.x + bet.x;
            ba.y = (gam.y + 1.f) * Av.y + bet.y;  br.y = (gam.y + 1.f) * Rv.y + bet.y;
            ba.z = (gam.z + 1.f) * Av.z + bet.z;  br.z = (gam.z + 1.f) * Rv.z + bet.z;
            ba.w = (gam.w + 1.f) * Av.w + bet.w;  br.w = (gam.w + 1.f) * Rv.w + bet.w;
            float R = ((float)d < Kthr) ? 1.f : 0.f;
            const float4* hp4 = (const float4*)sHp;
            float4 hp = hp4[nl * 16 + og];
            float inv = 1.f / (sRs[nl] + 1e-5f + 1.f);
            float bx = 0.1f * (R * ba.x - (1.f - R) * br.x);
            float by = 0.1f * (R * ba.y - (1.f - R) * br.y);
            float bz = 0.1f * (R * ba.z - (1.f - R) * br.z);
            float bw = 0.1f * (R * ba.w - (1.f - R) * br.w);
            o4.x = lrelu((hp.x + bx) * inv);
            o4.y = lrelu((hp.y + by) * inv);
            o4.z = lrelu((hp.z + bz) * inv);
            o4.w = lrelu((hp.w + bw) * inv);
            pa = ba.x * ba.x + ba.y * ba.y + ba.z * ba.z + ba.w * ba.w;
            pr = br.x * br.x + br.y * br.y + br.z * br.z + br.w * br.w;
        }
        #pragma unroll
        for (int o = 8; o; o >>= 1) {
            pa += __shfl_down_sync(0xFFFFFFFFu, pa, o, 16);
            pr += __shfl_down_sync(0xFFFFFFFFu, pr, o, 16);
        }
        if (node < Nn) {
            ((float4*)out)[node * 16 + og] = o4;
            if (og == 0) { g_nadd[node] = sqrtf(pa); g_nrev[node] = sqrtf(pr); }
        }
    }
}

// ---------------- L: loss reductions over idx -------------------------------
__global__ void k_loss(const int* __restrict__ degree, const int* __restrict__ idx,
                       float* __restrict__ out) {
    __shared__ float sb[256], sf[256];
    float Kthr = g_Kthr;
    float lb = 0.f, lf = 0.f;
    for (int i = threadIdx.x; i < NIDX; i += 256) {
        int r = idx[i];
        int d = degree[r];
        bool R = ((float)d) < Kthr;
        lb += R ? g_nadd[r] : g_nrev[r];
        lf += g_ngamtab[d] + g_nbettab[d];
    }
    sb[threadIdx.x] = lb; sf[threadIdx.x] = lf;
    __syncthreads();
    for (int s = 128; s; s >>= 1) {
        if (threadIdx.x < (unsigned)s) {
            sb[threadIdx.x] += sb[threadIdx.x + s];
            sf[threadIdx.x] += sf[threadIdx.x + s];
        }
        __syncthreads();
    }
    if (threadIdx.x == 0) {
        out[Nn * OUTF]     = sb[0] / (float)NIDX;
        out[Nn * OUTF + 1] = sf[0] / (float)NIDX;
    }
}

// ---------------- launch -----------------------------------------------------
extern "C" void kernel_launch(void* const* d_in, const int* in_sizes, int n_in,
                              void* d_out, int out_size) {
    const float* x      = (const float*)d_in[0];
    const float* W      = (const float*)d_in[1];
    const float* b      = (const float*)d_in[2];
    const float* a      = (const float*)d_in[3];
    const float* Wg     = (const float*)d_in[4];
    const float* Wb     = (const float*)d_in[5];
    const float* bg     = (const float*)d_in[6];
    const float* bb     = (const float*)d_in[7];
    const float* Wadd   = (const float*)d_in[8];
    const float* Wrev   = (const float*)d_in[9];
    const float* PE     = (const float*)d_in[10];
    const int*   edge   = (const int*)d_in[11];
    const int*   degree = (const int*)d_in[12];
    const int*   idx    = (const int*)d_in[13];
    float* out = (float*)d_out;

    cudaFuncSetAttribute(k_sh, cudaFuncAttributeMaxDynamicSharedMemorySize, SH_SMEM);
    cudaFuncSetAttribute(k_gf, cudaFuncAttributeMaxDynamicSharedMemorySize, GF_SMEM);

    k_ph<<<SBLK + NBLK + 64 + 64, 256>>>(edge, degree, W, Wadd, Wrev, Wg, Wb, bg, bb, PE);
    k_scan1<<<NBLK + 1, 256>>>();
    k_scan3b<<<NBLK, 256>>>();
    k_sh<<<SHBLK, 256, SH_SMEM>>>(edge, x, b, a);
    k_gf<<<GBLK, 256, GF_SMEM>>>(degree, out);
    if (out_size >= Nn * OUTF + 2)
        k_loss<<<1, 256>>>(degree, idx, out);
}

// round 16
// speedup vs baseline: 1.2424x; 1.0137x over previous
#include <cuda_runtime.h>
#include <cuda_fp16.h>
#include <math.h>

#define Nn   50000
#define Ee   1600000
#define INF  128
#define OUTF 64
#define NIDX 5000
#define NBLK 196        // ceil(Nn/256)
#define HBLK2 782       // ceil(Nn/64)
#define GBLK 1563       // ceil(Nn/32)
#define SBLK 1563       // ceil(Ee/4/256)
#define SHBLK 2345      // SBLK + HBLK2

// ---------------- scratch (device globals) ----------------------------------
__device__ uint2  g_hh[Nn * 16];      // h as fp16: 16 x uint2 = 64 halves per node
__device__ float  g_s[Nn];
__device__ float  g_t[Nn];
__device__ float  g_nadd[Nn];
__device__ float  g_nrev[Nn];
__device__ float4 g_gamtab4[256 * 16];
__device__ float4 g_bettab4[256 * 16];
__device__ float  g_ngamtab[256];
__device__ float  g_nbettab[256];
__device__ float  g_Wt[INF * OUTF];
__device__ float  g_WaT[OUTF * OUTF];
__device__ float  g_WrT[OUTF * OUTF];
__device__ int    g_cnt[Nn];          // zero at module load; re-zeroed by k_scanall
__device__ int    g_off[Nn + 1];
__device__ int    g_cur[Nn];
__device__ int    g_dsts[Ee];
__device__ int    g_bsum[NBLK];
__device__ int    g_dpart[NBLK];
__device__ int    g_arrive;           // scan barrier counter (reset by k_ph)
__device__ float  g_Kthr;

__device__ __forceinline__ float lrelu(float v) { return v > 0.f ? v : 0.01f * v; }

// ---------------- PH: hist + degree partials + transposes + gbtab -----------
__global__ void k_ph(const int* __restrict__ edge, const int* __restrict__ degree,
                     const float* __restrict__ W, const float* __restrict__ Wa,
                     const float* __restrict__ Wr, const float* __restrict__ Wg_,
                     const float* __restrict__ Wb_, const float* __restrict__ bg,
                     const float* __restrict__ bb, const float* __restrict__ PE) {
    int blk = blockIdx.x, tid = threadIdx.x;
    if (blk < SBLK) {                             // ---- edge histogram (int4) ----
        int t = blk * 256 + tid;
        if (t < Ee / 4) {
            int4 e = ((const int4*)edge)[t];
            atomicAdd(&g_cnt[e.x], 1);
            atomicAdd(&g_cnt[e.y], 1);
            atomicAdd(&g_cnt[e.z], 1);
            atomicAdd(&g_cnt[e.w], 1);
        }
        return;
    }
    if (blk < SBLK + NBLK) {                      // ---- degree partial sums ----
        __shared__ int ws[8];
        int bb2 = blk - SBLK;
        int t = bb2 * 256 + tid;
        int d = (t < Nn) ? degree[t] : 0;
        #pragma unroll
        for (int o = 16; o; o >>= 1) d += __shfl_down_sync(0xFFFFFFFFu, d, o);
        int lane = tid & 31, w = tid >> 5;
        if (lane == 0) ws[w] = d;
        __syncthreads();
        if (tid == 0) {
            int s = 0;
            #pragma unroll
            for (int q = 0; q < 8; q++) s += ws[q];
            g_dpart[bb2] = s;
        }
        return;
    }
    if (blk < SBLK + NBLK + 64) {                 // ---- weight transposes ----
        int t = (blk - SBLK - NBLK) * 256 + tid;
        if (t == 0) g_arrive = 0;                 // reset scan barrier each replay
        if (t < 8192) {
            int k = t >> 6, j = t & 63;
            g_Wt[t] = W[j * 128 + k];
        } else if (t < 12288) {
            int p = t - 8192; int k = p >> 6, j = p & 63;
            g_WaT[p] = Wa[j * 64 + k];
        } else {
            int p = t - 12288; int k = p >> 6, j = p & 63;
            g_WrT[p] = Wr[j * 64 + k];
        }
        return;
    }
    // ---- gamma/beta tables over 256 degrees ----
    __shared__ float Wg[4096], Wb[4096];
    __shared__ float ms[4][64];
    __shared__ float pG[8], pB[8];
    for (int p = tid; p < 4096; p += 256) { Wg[p] = Wg_[p]; Wb[p] = Wb_[p]; }
    int local = tid >> 6, j = tid & 63;
    int d = (blk - SBLK - NBLK - 64) * 4 + local;
    ms[local][j] = PE[d * 64 + j];
    __syncthreads();
    float ag = bg[j], ab = bb[j];
    #pragma unroll
    for (int k = 0; k < 64; k++) {
        float m = ms[local][k];
        ag += m * Wg[k * 64 + j];
        ab += m * Wb[k * 64 + j];
    }
    float gam = lrelu(ag), bet = lrelu(ab);
    ((float*)g_gamtab4)[d * 64 + j] = gam;
    ((float*)g_bettab4)[d * 64 + j] = bet;
    float pg = gam * gam, pb = bet * bet;
    #pragma unroll
    for (int o = 16; o; o >>= 1) {
        pg += __shfl_down_sync(0xFFFFFFFFu, pg, o);
        pb += __shfl_down_sync(0xFFFFFFFFu, pb, o);
    }
    int w = tid >> 5;
    if ((tid & 31) == 0) { pG[w] = pg; pB[w] = pb; }
    __syncthreads();
    if (j == 0) {
        g_ngamtab[d] = sqrtf(pG[2 * local] + pG[2 * local + 1]);
        g_nbettab[d] = sqrtf(pB[2 * local] + pB[2 * local + 1]);
    }
}

// ---------------- SCAN: single-pass scan with device-wide barrier -----------
// NBLK+1 blocks, all co-resident (196 tiny blocks << 1 wave) -> spin is safe.
__global__ void k_scanall() {
    __shared__ int ws[8];
    int tid = threadIdx.x;
    int lane = tid & 31, w = tid >> 5;
    if (blockIdx.x == NBLK) {                     // ---- Kthr reduction ----
        int v = (tid < NBLK) ? g_dpart[tid] : 0;
        #pragma unroll
        for (int o = 16; o; o >>= 1) v += __shfl_down_sync(0xFFFFFFFFu, v, o);
        if (lane == 0) ws[w] = v;
        __syncthreads();
        if (tid == 0) {
            int s = 0;
            #pragma unroll
            for (int q = 0; q < 8; q++) s += ws[q];
            g_Kthr = (float)((double)s / (double)Nn);
        }
        return;
    }
    int i = blockIdx.x * 256 + tid;
    int v = (i < Nn) ? g_cnt[i] : 0;
    // phase A: block sum -> publish -> device barrier
    {
        int s = v;
        #pragma unroll
        for (int o = 16; o; o >>= 1) s += __shfl_down_sync(0xFFFFFFFFu, s, o);
        if (lane == 0) ws[w] = s;
        __syncthreads();
        if (tid == 0) {
            int t = 0;
            #pragma unroll
            for (int q = 0; q < 8; q++) t += ws[q];
            g_bsum[blockIdx.x] = t;
            __threadfence();
            atomicAdd(&g_arrive, 1);
            while (atomicAdd(&g_arrive, 0) < NBLK) { }
        }
        __syncthreads();
        __threadfence();
    }
    // phase B1: replicated scan of 196 block sums
    __shared__ int base_s, tot_s;
    {
        int bv = (tid < NBLK) ? g_bsum[tid] : 0;
        int orig = bv;
        #pragma unroll
        for (int o = 1; o < 32; o <<= 1) { int u = __shfl_up_sync(0xFFFFFFFFu, bv, o); if (lane >= o) bv += u; }
        if (lane == 31) ws[w] = bv;
        __syncthreads();
        if (w == 0 && lane < 8) {
            int u = ws[lane];
            #pragma unroll
            for (int o = 1; o < 8; o <<= 1) { int z = __shfl_up_sync(0xFFu, u, o); if (lane >= o) u += z; }
            ws[lane] = u;
        }
        __syncthreads();
        int incl = bv + (w ? ws[w - 1] : 0);
        if (tid == (int)blockIdx.x) base_s = incl - orig;
        if (tid == NBLK - 1) tot_s = incl;
        __syncthreads();
    }
    // phase B2: local intra-block scan + write offsets + re-zero cnt
    int c = v, corig = v;
    #pragma unroll
    for (int o = 1; o < 32; o <<= 1) { int u = __shfl_up_sync(0xFFFFFFFFu, c, o); if (lane >= o) c += u; }
    if (lane == 31) ws[w] = c;
    __syncthreads();
    if (w == 0 && lane < 8) {
        int u = ws[lane];
        #pragma unroll
        for (int o = 1; o < 8; o <<= 1) { int z = __shfl_up_sync(0xFFu, u, o); if (lane >= o) u += z; }
        ws[lane] = u;
    }
    __syncthreads();
    int excl = c - corig + (w ? ws[w - 1] : 0) + base_s;
    if (i < Nn) {
        g_off[i] = excl; g_cur[i] = excl;
        g_cnt[i] = 0;
    }
    if (blockIdx.x == 0 && tid == 0) g_off[Nn] = tot_s;
}

// ---------------- SH: scatter + h-GEMM, roles INTERLEAVED across blocks ------
#define SH_SMEM 49152
__global__ void __launch_bounds__(256) k_sh(const int* __restrict__ edge,
                                            const float* __restrict__ x,
                                            const float* __restrict__ b,
                                            const float* __restrict__ a) {
    extern __shared__ float4 sh4[];
    float4* Ws = sh4;            // 128*16 float4 = 32KB
    float4* xs = sh4 + 2048;     // 64 nodes * 16 kq float4 = 16KB (reused 2x)
    int blk = blockIdx.x;
    int rem = blk % 3;
    if (rem != 1) {                   // -------- scatter branch --------
        int sidx = 2 * (blk / 3) + ((rem == 2) ? 1 : 0);
        int t = sidx * 256 + threadIdx.x;
        if (t < Ee / 4) {
            int4 s4 = ((const int4*)edge)[t];
            int4 d4 = ((const int4*)(edge + Ee))[t];
            int p;
            p = atomicAdd(&g_cur[s4.x], 1); g_dsts[p] = d4.x;
            p = atomicAdd(&g_cur[s4.y], 1); g_dsts[p] = d4.y;
            p = atomicAdd(&g_cur[s4.z], 1); g_dsts[p] = d4.z;
            p = atomicAdd(&g_cur[s4.w], 1); g_dsts[p] = d4.w;
        }
        return;
    }
    // -------- h = (xW^T+b)*8 ; s,t projections : 64 nodes, 4 per thread ------
    int gidx = blk / 3;               // 0..781
    int tid = threadIdx.x;
    const float4* Wt4 = (const float4*)g_Wt;
    for (int p = tid; p < 2048; p += 256) Ws[p] = Wt4[p];
    int n0 = gidx * 64;
    const float4* x4 = (const float4*)x;

    int og = tid & 15, ng = tid >> 4;
    int nbase = 4 * ng;
    float4 acc0 = make_float4(0.f, 0.f, 0.f, 0.f);
    float4 acc1 = acc0, acc2 = acc0, acc3 = acc0;

    #pragma unroll
    for (int hf = 0; hf < 2; hf++) {
        __syncthreads();
        for (int p = tid; p < 1024; p += 256) {
            int n = p >> 4, kq = p & 15;
            int node = n0 + n;
            xs[p] = (node < Nn) ? x4[node * 32 + hf * 16 + kq]
                                : make_float4(0.f, 0.f, 0.f, 0.f);
        }
        __syncthreads();
        #pragma unroll 4
        for (int kq = 0; kq < 16; kq++) {
            int kg = hf * 16 + kq;
            float4 w0 = Ws[(4 * kg + 0) * 16 + og];
            float4 w1 = Ws[(4 * kg + 1) * 16 + og];
            float4 w2 = Ws[(4 * kg + 2) * 16 + og];
            float4 w3 = Ws[(4 * kg + 3) * 16 + og];
            float4 x0 = xs[(nbase + 0) * 16 + kq];
            float4 x1 = xs[(nbase + 1) * 16 + kq];
            float4 x2 = xs[(nbase + 2) * 16 + kq];
            float4 x3 = xs[(nbase + 3) * 16 + kq];
            acc0.x += x0.x * w0.x + x0.y * w1.x + x0.z * w2.x + x0.w * w3.x;
            acc0.y += x0.x * w0.y + x0.y * w1.y + x0.z * w2.y + x0.w * w3.y;
            acc0.z += x0.x * w0.z + x0.y * w1.z + x0.z * w2.z + x0.w * w3.z;
            acc0.w += x0.x * w0.w + x0.y * w1.w + x0.z * w2.w + x0.w * w3.w;
            acc1.x += x1.x * w0.x + x1.y * w1.x + x1.z * w2.x + x1.w * w3.x;
            acc1.y += x1.x * w0.y + x1.y * w1.y + x1.z * w2.y + x1.w * w3.y;
            acc1.z += x1.x * w0.z + x1.y * w1.z + x1.z * w2.z + x1.w * w3.z;
            acc1.w += x1.x * w0.w + x1.y * w1.w + x1.z * w2.w + x1.w * w3.w;
            acc2.x += x2.x * w0.x + x2.y * w1.x + x2.z * w2.x + x2.w * w3.x;
            acc2.y += x2.x * w0.y + x2.y * w1.y + x2.z * w2.y + x2.w * w3.y;
            acc2.z += x2.x * w0.z + x2.y * w1.z + x2.z * w2.z + x2.w * w3.z;
            acc2.w += x2.x * w0.w + x2.y * w1.w + x2.z * w2.w + x2.w * w3.w;
            acc3.x += x3.x * w0.x + x3.y * w1.x + x3.z * w2.x + x3.w * w3.x;
            acc3.y += x3.x * w0.y + x3.y * w1.y + x3.z * w2.y + x3.w * w3.y;
            acc3.z += x3.x * w0.z + x3.y * w1.z + x3.z * w2.z + x3.w * w3.z;
            acc3.w += x3.x * w0.w + x3.y * w1.w + x3.z * w2.w + x3.w * w3.w;
        }
    }
    float4 b4  = ((const float4*)b)[og];
    float4 as4 = ((const float4*)a)[og];
    float4 at4 = ((const float4*)a)[16 + og];
    #pragma unroll
    for (int i = 0; i < 4; i++) {
        float4 A = (i == 0) ? acc0 : (i == 1) ? acc1 : (i == 2) ? acc2 : acc3;
        float4 h = make_float4((A.x + b4.x) * 8.f, (A.y + b4.y) * 8.f,
                               (A.z + b4.z) * 8.f, (A.w + b4.w) * 8.f);
        int node = n0 + nbase + i;
        if (node < Nn) {
            __half2 p01 = __float22half2_rn(make_float2(h.x, h.y));
            __half2 p23 = __float22half2_rn(make_float2(h.z, h.w));
            uint2 st;
            st.x = *reinterpret_cast<unsigned int*>(&p01);
            st.y = *reinterpret_cast<unsigned int*>(&p23);
            g_hh[node * 16 + og] = st;
        }
        float sv = h.x * as4.x + h.y * as4.y + h.z * as4.z + h.w * as4.w;
        float tv = h.x * at4.x + h.y * at4.y + h.z * at4.z + h.w * at4.w;
        #pragma unroll
        for (int o = 8; o; o >>= 1) {
            sv += __shfl_down_sync(0xFFFFFFFFu, sv, o, 16);
            tv += __shfl_down_sync(0xFFFFFFFFu, tv, o, 16);
        }
        if (og == 0 && node < Nn) { g_s[node] = sv; g_t[node] = tv; }
    }
}

// ---------------- GF: fused gather (smem-staged dst/ev) + epilogue -----------
#define GF_SMEM 51584
__global__ void __launch_bounds__(256) k_gf(const int* __restrict__ degree,
                                            float* __restrict__ out) {
    extern __shared__ float sm[];
    float4* WsA  = (float4*)sm;            // 16KB
    float4* WsR  = WsA + 1024;             // 16KB
    float*  sAgg = sm + 8192;              // 8KB
    float*  sHp  = sAgg + 2048;            // 8KB
    float*  sRs  = sHp + 2048;
    float*  sInv = sRs + 32;
    int*    sDeg = (int*)(sInv + 32);
    float2* sPair = (float2*)(sm + 12384); // 8 warps * 32 * float2 = 2KB
    int tid = threadIdx.x;
    const float4* Wa4 = (const float4*)g_WaT;
    const float4* Wr4 = (const float4*)g_WrT;
    for (int p = tid; p < 1024; p += 256) { WsA[p] = Wa4[p]; WsR[p] = Wr4[p]; }
    int n0 = blockIdx.x * 32;
    if (tid < 32) {
        int node = n0 + tid;
        int d = (node < Nn) ? degree[node] : 1;
        sDeg[tid] = d;
        sInv[tid] = (d == 0) ? 0.f : 1.f / (float)d;
    }
    int w = tid >> 5, lane = tid & 31;
    int lq = lane & 15, half = lane >> 4;
    float2* myPair = sPair + w * 32;
    #pragma unroll
    for (int k = 0; k < 4; k++) {
        int nl = w + 8 * k;
        int node = n0 + nl;
        float4 acc  = make_float4(0.f, 0.f, 0.f, 0.f);
        float4 wacc = acc;
        float rs = 0.f;
        if (node < Nn) {
            int s0 = g_off[node], s1 = g_off[node + 1];
            float ssrc = g_s[node];
            for (int base = s0; base < s1; base += 32) {
                int m = s1 - base; if (m > 32) m = 32;
                if (lane < m) {
                    int dst = g_dsts[base + lane];
                    float z = ssrc + g_t[dst];
                    float ev = __expf(-(z > 0.f ? z : 0.01f * z));
                    rs += ev;
                    myPair[lane] = make_float2(__int_as_float(dst), ev);
                }
                __syncwarp();
                if (m == 32) {
                    #pragma unroll 8
                    for (int p = 0; p < 16; p++) {
                        float2 pr = myPair[2 * p + half];
                        int dd = __float_as_int(pr.x);
                        float e = pr.y;
                        uint2 raw = g_hh[dd * 16 + lq];
                        float2 f01 = __half22float2(*reinterpret_cast<__half2*>(&raw.x));
                        float2 f23 = __half22float2(*reinterpret_cast<__half2*>(&raw.y));
                        acc.x += f01.x;  acc.y += f01.y;  acc.z += f23.x;  acc.w += f23.y;
                        wacc.x += e * f01.x; wacc.y += e * f01.y;
                        wacc.z += e * f23.x; wacc.w += e * f23.y;
                    }
                } else {
                    int pm = (m + 1) >> 1;
                    for (int p = 0; p < pm; p++) {
                        int j = 2 * p + half;
                        if (j < m) {
                            float2 pr = myPair[j];
                            int dd = __float_as_int(pr.x);
                            float e = pr.y;
                            uint2 raw = g_hh[dd * 16 + lq];
                            float2 f01 = __half22float2(*reinterpret_cast<__half2*>(&raw.x));
                            float2 f23 = __half22float2(*reinterpret_cast<__half2*>(&raw.y));
                            acc.x += f01.x;  acc.y += f01.y;  acc.z += f23.x;  acc.w += f23.y;
                            wacc.x += e * f01.x; wacc.y += e * f01.y;
                            wacc.z += e * f23.x; wacc.w += e * f23.y;
                        }
                    }
                }
                __syncwarp();
            }
        }
        acc.x  += __shfl_down_sync(0xFFFFFFFFu, acc.x, 16);
        acc.y  += __shfl_down_sync(0xFFFFFFFFu, acc.y, 16);
        acc.z  += __shfl_down_sync(0xFFFFFFFFu, acc.z, 16);
        acc.w  += __shfl_down_sync(0xFFFFFFFFu, acc.w, 16);
        wacc.x += __shfl_down_sync(0xFFFFFFFFu, wacc.x, 16);
        wacc.y += __shfl_down_sync(0xFFFFFFFFu, wacc.y, 16);
        wacc.z += __shfl_down_sync(0xFFFFFFFFu, wacc.z, 16);
        wacc.w += __shfl_down_sync(0xFFFFFFFFu, wacc.w, 16);
        if (lane < 16) {
            ((float4*)sAgg)[nl * 16 + lq] = acc;
            ((float4*)sHp)[nl * 16 + lq]  = wacc;
        }
        #pragma unroll
        for (int o = 16; o; o >>= 1) rs += __shfl_down_sync(0xFFFFFFFFu, rs, o);
        if (lane == 0) sRs[nl] = rs;
    }
    __syncthreads();
    for (int p = tid; p < 2048; p += 256) sAgg[p] *= sInv[p >> 6];
    __syncthreads();

    int og = tid & 15, ng = tid >> 4;
    int na = 2 * ng, nb = na + 1;
    const float4* is4 = (const float4*)sAgg;
    float4 Aa = make_float4(0.f, 0.f, 0.f, 0.f), Ra = Aa, Ab = Aa, Rb = Aa;
    #pragma unroll 4
    for (int kq = 0; kq < 16; kq++) {
        float4 xa = is4[na * 16 + kq];
        float4 xb = is4[nb * 16 + kq];
        #pragma unroll
        for (int r = 0; r < 4; r++) {
            float4 wa = WsA[(4 * kq + r) * 16 + og];
            float4 wr = WsR[(4 * kq + r) * 16 + og];
            float xav = (r == 0) ? xa.x : (r == 1) ? xa.y : (r == 2) ? xa.z : xa.w;
            float xbv = (r == 0) ? xb.x : (r == 1) ? xb.y : (r == 2) ? xb.z : xb.w;
            Aa.x += xav * wa.x; Aa.y += xav * wa.y; Aa.z += xav * wa.z; Aa.w += xav * wa.w;
            Ra.x += xav * wr.x; Ra.y += xav * wr.y; Ra.z += xav * wr.z; Ra.w += xav * wr.w;
            Ab.x += xbv * wa.x; Ab.y += xbv * wa.y; Ab.z += xbv * wa.z; Ab.w += xbv * wa.w;
            Rb.x += xbv * wr.x; Rb.y += xbv * wr.y; Rb.z += xbv * wr.z; Rb.w += xbv * wr.w;
        }
    }
    float Kthr = g_Kthr;

    #pragma unroll
    for (int hh = 0; hh < 2; hh++) {
        int nl = hh ? nb : na;
        int node = n0 + nl;
        float4 Av = hh ? Ab : Aa;
        float4 Rv = hh ? Rb : Ra;
        float pa = 0.f, pr = 0.f;
        float4 o4 = make_float4(0.f, 0.f, 0.f, 0.f);
        if (node < Nn) {
            int d = sDeg[nl];
            float4 gam = g_gamtab4[d * 16 + og];
            float4 bet = g_bettab4[d * 16 + og];
            float4 ba, br;
            ba.x = (gam.x + 1.f) * Av.x + bet.x;  br.x = (gam.x + 1.f) * Rv.x + bet.x;
            ba.y = (gam.y + 1.f) * Av.y + bet.y;  br.y = (gam.y + 1.f) * Rv.y + bet.y;
            ba.z = (gam.z + 1.f) * Av.z + bet.z;  br.z = (gam.z + 1.f) * Rv.z + bet.z;
            ba.w = (gam.w + 1.f) * Av.w + bet.w;  br.w = (gam.w + 1.f) * Rv.w + bet.w;
            float R = ((float)d < Kthr) ? 1.f : 0.f;
            const float4* hp4 = (const float4*)sHp;
            float4 hp = hp4[nl * 16 + og];
            float inv = 1.f / (sRs[nl] + 1e-5f + 1.f);
            float bx = 0.1f * (R * ba.x - (1.f - R) * br.x);
            float by = 0.1f * (R * ba.y - (1.f - R) * br.y);
            float bz = 0.1f * (R * ba.z - (1.f - R) * br.z);
            float bw = 0.1f * (R * ba.w - (1.f - R) * br.w);
            o4.x = lrelu((hp.x + bx) * inv);
            o4.y = lrelu((hp.y + by) * inv);
            o4.z = lrelu((hp.z + bz) * inv);
            o4.w = lrelu((hp.w + bw) * inv);
            pa = ba.x * ba.x + ba.y * ba.y + ba.z * ba.z + ba.w * ba.w;
            pr = br.x * br.x + br.y * br.y + br.z * br.z + br.w * br.w;
        }
        #pragma unroll
        for (int o = 8; o; o >>= 1) {
            pa += __shfl_down_sync(0xFFFFFFFFu, pa, o, 16);
            pr += __shfl_down_sync(0xFFFFFFFFu, pr, o, 16);
        }
        if (node < Nn) {
            ((float4*)out)[node * 16 + og] = o4;
            if (og == 0) { g_nadd[node] = sqrtf(pa); g_nrev[node] = sqrtf(pr); }
        }
    }
}

// ---------------- L: loss reductions over idx -------------------------------
__global__ void k_loss(const int* __restrict__ degree, const int* __restrict__ idx,
                       float* __restrict__ out) {
    __shared__ float sb[256], sf[256];
    float Kthr = g_Kthr;
    float lb = 0.f, lf = 0.f;
    for (int i = threadIdx.x; i < NIDX; i += 256) {
        int r = idx[i];
        int d = degree[r];
        bool R = ((float)d) < Kthr;
        lb += R ? g_nadd[r] : g_nrev[r];
        lf += g_ngamtab[d] + g_nbettab[d];
    }
    sb[threadIdx.x] = lb; sf[threadIdx.x] = lf;
    __syncthreads();
    for (int s = 128; s; s >>= 1) {
        if (threadIdx.x < (unsigned)s) {
            sb[threadIdx.x] += sb[threadIdx.x + s];
            sf[threadIdx.x] += sf[threadIdx.x + s];
        }
        __syncthreads();
    }
    if (threadIdx.x == 0) {
        out[Nn * OUTF]     = sb[0] / (float)NIDX;
        out[Nn * OUTF + 1] = sf[0] / (float)NIDX;
    }
}

// ---------------- launch -----------------------------------------------------
extern "C" void kernel_launch(void* const* d_in, const int* in_sizes, int n_in,
                              void* d_out, int out_size) {
    const float* x      = (const float*)d_in[0];
    const float* W      = (const float*)d_in[1];
    const float* b      = (const float*)d_in[2];
    const float* a      = (const float*)d_in[3];
    const float* Wg     = (const float*)d_in[4];
    const float* Wb     = (const float*)d_in[5];
    const float* bg     = (const float*)d_in[6];
    const float* bb     = (const float*)d_in[7];
    const float* Wadd   = (const float*)d_in[8];
    const float* Wrev   = (const float*)d_in[9];
    const float* PE     = (const float*)d_in[10];
    const int*   edge   = (const int*)d_in[11];
    const int*   degree = (const int*)d_in[12];
    const int*   idx    = (const int*)d_in[13];
    float* out = (float*)d_out;

    cudaFuncSetAttribute(k_sh, cudaFuncAttributeMaxDynamicSharedMemorySize, SH_SMEM);
    cudaFuncSetAttribute(k_gf, cudaFuncAttributeMaxDynamicSharedMemorySize, GF_SMEM);

    k_ph<<<SBLK + NBLK + 64 + 64, 256>>>(edge, degree, W, Wadd, Wrev, Wg, Wb, bg, bb, PE);
    k_scanall<<<NBLK + 1, 256>>>();
    k_sh<<<SHBLK, 256, SH_SMEM>>>(edge, x, b, a);
    k_gf<<<GBLK, 256, GF_SMEM>>>(degree, out);
    if (out_size >= Nn * OUTF + 2)
        k_loss<<<1, 256>>>(degree, idx, out);
}